// round 1
// baseline (speedup 1.0000x reference)
#include <cuda_runtime.h>
#include <cuda_bf16.h>
#include <math.h>

// ---------------- problem constants ----------------
#define BATCH 64
#define TSTEPS 20
#define CIN 25
#define HID 64
#define SP 25          // H = W = 25
#define NPIX 625       // 25*25
#define GATES 256      // 4*HID
#define POOLD 12
#define FEAT 9216      // 64*12*12
#define FC1N 128
#define FC2N 64

// ---------------- scratch (device globals, no allocation) ----------------
__device__ float g_xn[(long)TSTEPS * BATCH * CIN * NPIX];    // time-major normed input
__device__ float g_z [(long)BATCH * GATES * NPIX];           // gate pre-activations
__device__ float g_h0[(long)BATCH * HID * NPIX];
__device__ float g_c0[(long)BATCH * HID * NPIX];
__device__ float g_h1[(long)BATCH * HID * NPIX];
__device__ float g_c1[(long)BATCH * HID * NPIX];
__device__ float g_y [(long)BATCH * HID * NPIX];             // conv1 output
__device__ float g_pool[(long)BATCH * FEAT];
__device__ float g_f1[BATCH * FC1N];
__device__ float g_f2[BATCH * FC2N];
__device__ float g_f3[BATCH * 2];

// ---------------- zero the recurrent state ----------------
__global__ void zero_state_kernel(float* a, float* b, float* c, float* d, int n) {
    int i = blockIdx.x * blockDim.x + threadIdx.x;
    if (i < n) { a[i] = 0.f; b[i] = 0.f; c[i] = 0.f; d[i] = 0.f; }
}

// ---------------- LayerNorm over channel dim ----------------
// x: [B,T,C,H,W] -> g_xn: [T,B,C,H,W]
__global__ void ln_kernel(const float* __restrict__ x,
                          const float* __restrict__ gamma,
                          const float* __restrict__ beta,
                          float* __restrict__ xn) {
    int idx = blockIdx.x * blockDim.x + threadIdx.x;   // over B*T*NPIX
    if (idx >= BATCH * TSTEPS * NPIX) return;
    int p = idx % NPIX;
    int t = (idx / NPIX) % TSTEPS;
    int b = idx / (NPIX * TSTEPS);
    const float* base = x + ((long)(b * TSTEPS + t) * CIN) * NPIX + p;
    float v[CIN];
    float s = 0.f;
    #pragma unroll
    for (int c = 0; c < CIN; c++) { v[c] = base[c * NPIX]; s += v[c]; }
    float mu = s * (1.f / CIN);
    float q = 0.f;
    #pragma unroll
    for (int c = 0; c < CIN; c++) { float d = v[c] - mu; q += d * d; }
    float rs = rsqrtf(q * (1.f / CIN) + 1e-5f);
    float* ob = xn + ((long)(t * BATCH + b) * CIN) * NPIX + p;
    #pragma unroll
    for (int c = 0; c < CIN; c++) ob[c * NPIX] = (v[c] - mu) * rs * gamma[c] + beta[c];
}

// ---------------- implicit-GEMM 3x3 SAME conv ----------------
// out[img][n][p] = bias[n] + sum over virtual-concat(in0:C0, in1:C1) channels
// weight element: W[n*ldw + (cc + coff)*9 + r], where cc is concat channel idx.
// GEMM: M = n_img*625, N = Cout, K = (C0+C1)*9
#define BM 128
#define BN 64
#define BK 8
#define TM 8
#define TN 4

__global__ __launch_bounds__(256)
void convgemm_kernel(const float* __restrict__ in0, int C0, int coff0,
                     const float* __restrict__ in1, int C1, int coff1,
                     const float* __restrict__ W, int ldw,
                     const float* __restrict__ bias,
                     float* __restrict__ out,
                     int n_img, int Cout, int relu) {
    const int Ktot = (C0 + C1) * 9;
    const int M = n_img * NPIX;
    const int m0 = blockIdx.x * BM;
    const int n0 = blockIdx.y * BN;

    __shared__ float As[BK][BM];
    __shared__ float Bs[BK][BN];

    const int tid = threadIdx.x;       // 0..255
    const int tx = tid & 15;           // 16 cols
    const int ty = tid >> 4;           // 16 rows

    // Precompute A-load slot geometry (4 slots of 256 -> 1024 = BM*BK)
    int a_mm[4], a_kk[4], a_m[4], a_img[4], a_y[4], a_x[4];
    #pragma unroll
    for (int l = 0; l < 4; l++) {
        int idx = tid + l * 256;
        a_mm[l] = idx & (BM - 1);
        a_kk[l] = idx >> 7;
        int m = m0 + a_mm[l];
        a_m[l] = m;
        int mc = m < M ? m : M - 1;
        a_img[l] = mc / NPIX;
        int p = mc - a_img[l] * NPIX;
        a_y[l] = p / SP;
        a_x[l] = p - a_y[l] * SP;
    }
    // B-load slots (2 slots of 256 -> 512 = BK*BN)
    int b_nn[2], b_kk[2];
    #pragma unroll
    for (int l = 0; l < 2; l++) {
        int idx = tid + l * 256;
        b_nn[l] = idx & (BN - 1);
        b_kk[l] = idx >> 6;
    }

    float acc[TM][TN];
    #pragma unroll
    for (int i = 0; i < TM; i++)
        #pragma unroll
        for (int j = 0; j < TN; j++) acc[i][j] = 0.f;

    for (int k0 = 0; k0 < Ktot; k0 += BK) {
        // --- load A tile (implicit im2col gather) ---
        #pragma unroll
        for (int l = 0; l < 4; l++) {
            int k = k0 + a_kk[l];
            float v = 0.f;
            if (a_m[l] < M && k < Ktot) {
                int cc = k / 9;
                int r = k - cc * 9;
                int ky = r / 3;
                int kx = r - ky * 3;
                int iy = a_y[l] + ky - 1;
                int ix = a_x[l] + kx - 1;
                if ((unsigned)iy < (unsigned)SP && (unsigned)ix < (unsigned)SP) {
                    const float* src; int c, Cc;
                    if (cc < C0) { src = in0; c = cc;      Cc = C0; }
                    else         { src = in1; c = cc - C0; Cc = C1; }
                    v = src[((long)a_img[l] * Cc + c) * NPIX + iy * SP + ix];
                }
            }
            As[a_kk[l]][a_mm[l]] = v;
        }
        // --- load B tile (weights) ---
        #pragma unroll
        for (int l = 0; l < 2; l++) {
            int k = k0 + b_kk[l];
            int n = n0 + b_nn[l];
            float v = 0.f;
            if (k < Ktot && n < Cout) {
                int cc = k / 9;
                int r = k - cc * 9;
                int coff = (cc < C0) ? coff0 : (coff1 - C0);
                v = W[(long)n * ldw + (cc + coff) * 9 + r];
            }
            Bs[b_kk[l]][b_nn[l]] = v;
        }
        __syncthreads();

        #pragma unroll
        for (int kk = 0; kk < BK; kk++) {
            float4 b4 = *reinterpret_cast<const float4*>(&Bs[kk][tx * TN]);
            float4 a0 = *reinterpret_cast<const float4*>(&As[kk][ty * TM]);
            float4 a1 = *reinterpret_cast<const float4*>(&As[kk][ty * TM + 4]);
            float av[TM] = {a0.x, a0.y, a0.z, a0.w, a1.x, a1.y, a1.z, a1.w};
            float bv[TN] = {b4.x, b4.y, b4.z, b4.w};
            #pragma unroll
            for (int i = 0; i < TM; i++)
                #pragma unroll
                for (int j = 0; j < TN; j++)
                    acc[i][j] += av[i] * bv[j];
        }
        __syncthreads();
    }

    // --- epilogue ---
    #pragma unroll
    for (int i = 0; i < TM; i++) {
        int m = m0 + ty * TM + i;
        if (m >= M) continue;
        int img = m / NPIX;
        int p = m - img * NPIX;
        #pragma unroll
        for (int j = 0; j < TN; j++) {
            int n = n0 + tx * TN + j;
            if (n >= Cout) continue;
            float v = acc[i][j] + bias[n];
            if (relu) v = fmaxf(v, 0.f);
            out[((long)img * Cout + n) * NPIX + p] = v;
        }
    }
}

// ---------------- ConvLSTM gates ----------------
// z: [B, 4*HID, 625] gate order i,f,o,g ; h,c: [B, HID, 625]
__global__ void gates_kernel(const float* __restrict__ z,
                             float* __restrict__ h, float* __restrict__ c) {
    int idx = blockIdx.x * blockDim.x + threadIdx.x;
    if (idx >= BATCH * HID * NPIX) return;
    int p = idx % NPIX;
    int j = (idx / NPIX) % HID;
    int b = idx / (NPIX * HID);
    long zb = ((long)b * GATES + j) * NPIX + p;
    float zi = z[zb];
    float zf = z[zb + (long)HID * NPIX];
    float zo = z[zb + (long)2 * HID * NPIX];
    float zg = z[zb + (long)3 * HID * NPIX];
    float ig = 1.f / (1.f + expf(-zi));
    float fg = 1.f / (1.f + expf(-zf));
    float og = 1.f / (1.f + expf(-zo));
    float gg = tanhf(zg);
    float cn = fg * c[idx] + ig * gg;
    c[idx] = cn;
    h[idx] = og * tanhf(cn);
}

// ---------------- maxpool 2x2 stride 2 (VALID), NCHW-flatten ----------------
__global__ void pool_kernel(const float* __restrict__ y, float* __restrict__ out) {
    int idx = blockIdx.x * blockDim.x + threadIdx.x;
    if (idx >= BATCH * HID * POOLD * POOLD) return;
    int j = idx % POOLD;
    int i = (idx / POOLD) % POOLD;
    int ch = (idx / (POOLD * POOLD)) % HID;
    int b = idx / (POOLD * POOLD * HID);
    const float* p = y + ((long)(b * HID + ch)) * NPIX + (2 * i) * SP + 2 * j;
    float m = fmaxf(fmaxf(p[0], p[1]), fmaxf(p[SP], p[SP + 1]));
    out[(long)b * FEAT + ch * (POOLD * POOLD) + i * POOLD + j] = m;
}

// ---------------- FC: one warp per output element ----------------
__global__ void fc_kernel(const float* __restrict__ in, const float* __restrict__ w,
                          const float* __restrict__ b, float* __restrict__ out,
                          int M, int N, int K, int relu) {
    int warp = (blockIdx.x * blockDim.x + threadIdx.x) >> 5;
    int lane = threadIdx.x & 31;
    if (warp >= M * N) return;
    int m = warp / N, n = warp - m * N;
    const float* ir = in + (long)m * K;
    const float* wr = w + (long)n * K;
    float s = 0.f;
    for (int k = lane; k < K; k += 32) s += ir[k] * wr[k];
    #pragma unroll
    for (int o = 16; o; o >>= 1) s += __shfl_xor_sync(0xFFFFFFFFu, s, o);
    if (lane == 0) {
        s += b[n];
        if (relu) s = fmaxf(s, 0.f);
        out[(long)m * N + n] = s;
    }
}

// ---------------- log_softmax over 2 classes ----------------
__global__ void lsm_kernel(const float* __restrict__ in, float* __restrict__ out) {
    int m = blockIdx.x * blockDim.x + threadIdx.x;
    if (m >= BATCH) return;
    float a = in[2 * m], b = in[2 * m + 1];
    float mx = fmaxf(a, b);
    float l = mx + logf(expf(a - mx) + expf(b - mx));
    out[2 * m] = a - l;
    out[2 * m + 1] = b - l;
}

// ---------------- launch ----------------
extern "C" void kernel_launch(void* const* d_in, const int* in_sizes, int n_in,
                              void* d_out, int out_size) {
    const float* x   = (const float*)d_in[0];
    const float* lg  = (const float*)d_in[1];
    const float* lb  = (const float*)d_in[2];
    const float* w0  = (const float*)d_in[3];
    const float* b0  = (const float*)d_in[4];
    const float* w1  = (const float*)d_in[5];
    const float* b1  = (const float*)d_in[6];
    const float* wc  = (const float*)d_in[7];
    const float* bc  = (const float*)d_in[8];
    const float* wf1 = (const float*)d_in[9];
    const float* bf1 = (const float*)d_in[10];
    const float* wf2 = (const float*)d_in[11];
    const float* bf2 = (const float*)d_in[12];
    const float* wf3 = (const float*)d_in[13];
    const float* bf3 = (const float*)d_in[14];
    float* out = (float*)d_out;

    float *xn, *z, *h0, *c0, *h1, *c1, *y, *pool, *f1, *f2, *f3;
    cudaGetSymbolAddress((void**)&xn, g_xn);
    cudaGetSymbolAddress((void**)&z,  g_z);
    cudaGetSymbolAddress((void**)&h0, g_h0);
    cudaGetSymbolAddress((void**)&c0, g_c0);
    cudaGetSymbolAddress((void**)&h1, g_h1);
    cudaGetSymbolAddress((void**)&c1, g_c1);
    cudaGetSymbolAddress((void**)&y,  g_y);
    cudaGetSymbolAddress((void**)&pool, g_pool);
    cudaGetSymbolAddress((void**)&f1, g_f1);
    cudaGetSymbolAddress((void**)&f2, g_f2);
    cudaGetSymbolAddress((void**)&f3, g_f3);

    const int nstate = BATCH * HID * NPIX;                      // 2.56M
    zero_state_kernel<<<(nstate + 255) / 256, 256>>>(h0, c0, h1, c1, nstate);

    const int nln = BATCH * TSTEPS * NPIX;                      // 800k
    ln_kernel<<<(nln + 255) / 256, 256>>>(x, lg, lb, xn);

    const int M = BATCH * NPIX;                                 // 40000
    dim3 gridL((M + BM - 1) / BM, GATES / BN);                  // 313 x 4
    dim3 gridC((M + BM - 1) / BM, HID / BN);                    // 313 x 1
    const int ngate = BATCH * HID * NPIX;

    for (int t = 0; t < TSTEPS; t++) {
        const float* xt = xn + (long)t * BATCH * CIN * NPIX;
        // layer 0: virtual concat [x_t(25ch) | h0(64ch)], K = 801
        convgemm_kernel<<<gridL, 256>>>(xt, CIN, 0, h0, HID, CIN,
                                        w0, (CIN + HID) * 9, b0, z, BATCH, GATES, 0);
        gates_kernel<<<(ngate + 255) / 256, 256>>>(z, h0, c0);
        // layer 1: virtual concat [h0(64ch) | h1(64ch)], K = 1152
        convgemm_kernel<<<gridL, 256>>>(h0, HID, 0, h1, HID, HID,
                                        w1, (2 * HID) * 9, b1, z, BATCH, GATES, 0);
        gates_kernel<<<(ngate + 255) / 256, 256>>>(z, h1, c1);
    }

    // conv1 + relu
    convgemm_kernel<<<gridC, 256>>>(h1, HID, 0, (const float*)0, 0, 0,
                                    wc, HID * 9, bc, y, BATCH, HID, 1);
    // maxpool -> NCHW flatten
    const int npool = BATCH * HID * POOLD * POOLD;
    pool_kernel<<<(npool + 255) / 256, 256>>>(y, pool);

    // FC stack (warp per output)
    {
        int warps = BATCH * FC1N;
        fc_kernel<<<(warps * 32 + 255) / 256, 256>>>(pool, wf1, bf1, f1, BATCH, FC1N, FEAT, 1);
    }
    {
        int warps = BATCH * FC2N;
        fc_kernel<<<(warps * 32 + 255) / 256, 256>>>(f1, wf2, bf2, f2, BATCH, FC2N, FC1N, 1);
    }
    {
        int warps = BATCH * 2;
        fc_kernel<<<(warps * 32 + 255) / 256, 256>>>(f2, wf3, bf3, f3, BATCH, 2, FC2N, 0);
    }
    lsm_kernel<<<1, BATCH>>>(f3, out);
}

// round 3
// speedup vs baseline: 1.5143x; 1.5143x over previous
#include <cuda_runtime.h>
#include <cuda_bf16.h>
#include <math.h>
#include <cstdint>

// ---------------- problem constants ----------------
#define BATCH 64
#define TSTEPS 20
#define CIN 25
#define HID 64
#define SP 25
#define NPIX 625
#define GATES 256
#define POOLD 12
#define FEAT 9216
#define FC1N 128
#define FC2N 64

#define K0TOT ((CIN + HID) * 9)   // 801
#define K0PAD 832                 // 26 stages of 32
#define K1TOT (2 * HID * 9)       // 1152
#define K1PAD 1152                // 36 stages
#define KCTOT (HID * 9)           // 576
#define KCPAD 576                 // 18 stages

// ---------------- scratch (device globals, no allocation) ----------------
__device__ float g_xn[(long)TSTEPS * BATCH * CIN * NPIX];
__device__ float g_h0a[(long)BATCH * HID * NPIX];
__device__ float g_h0b[(long)BATCH * HID * NPIX];
__device__ float g_h1a[(long)BATCH * HID * NPIX];
__device__ float g_h1b[(long)BATCH * HID * NPIX];
__device__ float g_c0[(long)BATCH * HID * NPIX];
__device__ float g_c1[(long)BATCH * HID * NPIX];
__device__ float g_y [(long)BATCH * HID * NPIX];
__device__ float g_pool[(long)BATCH * FEAT];
__device__ float g_f1[BATCH * FC1N];
__device__ float g_f2[BATCH * FC2N];
__device__ float g_f3[BATCH * 2];
__device__ __align__(16) __nv_bfloat16 g_w0h[GATES * K0PAD];
__device__ __align__(16) __nv_bfloat16 g_w0l[GATES * K0PAD];
__device__ __align__(16) __nv_bfloat16 g_w1h[GATES * K1PAD];
__device__ __align__(16) __nv_bfloat16 g_w1l[GATES * K1PAD];
__device__ __align__(16) __nv_bfloat16 g_wch[HID * KCPAD];
__device__ __align__(16) __nv_bfloat16 g_wcl[HID * KCPAD];

// ---------------- helpers ----------------
__device__ __forceinline__ uint32_t smem_u32(const void* p) {
    uint32_t a;
    asm("{ .reg .u64 t; cvta.to.shared.u64 t, %1; cvt.u32.u64 %0, t; }" : "=r"(a) : "l"(p));
    return a;
}
#define LDSM4(r, a) \
    asm volatile("ldmatrix.sync.aligned.m8n8.x4.shared.b16 {%0,%1,%2,%3}, [%4];" \
        : "=r"((r)[0]), "=r"((r)[1]), "=r"((r)[2]), "=r"((r)[3]) : "r"(a))

__device__ __forceinline__ void mma_bf16(float* c, const uint32_t* a, const uint32_t* b) {
    asm volatile(
        "mma.sync.aligned.m16n8k16.row.col.f32.bf16.bf16.f32 "
        "{%0,%1,%2,%3}, {%4,%5,%6,%7}, {%8,%9}, {%0,%1,%2,%3};"
        : "+f"(c[0]), "+f"(c[1]), "+f"(c[2]), "+f"(c[3])
        : "r"(a[0]), "r"(a[1]), "r"(a[2]), "r"(a[3]), "r"(b[0]), "r"(b[1]));
}

__device__ __forceinline__ float sigm(float x) { return 1.f / (1.f + __expf(-x)); }
__device__ __forceinline__ float tanh_acc(float x) {
    float e = __expf(-2.f * fabsf(x));
    float t = (1.f - e) / (1.f + e);
    return copysignf(t, x);
}

// ---------------- small kernels ----------------
__global__ void zero_state_kernel(float* a, float* b, float* c, float* d, int n) {
    int i = blockIdx.x * blockDim.x + threadIdx.x;
    if (i < n) { a[i] = 0.f; b[i] = 0.f; c[i] = 0.f; d[i] = 0.f; }
}

__global__ void ln_kernel(const float* __restrict__ x,
                          const float* __restrict__ gamma,
                          const float* __restrict__ beta,
                          float* __restrict__ xn) {
    int idx = blockIdx.x * blockDim.x + threadIdx.x;
    if (idx >= BATCH * TSTEPS * NPIX) return;
    int p = idx % NPIX;
    int t = (idx / NPIX) % TSTEPS;
    int b = idx / (NPIX * TSTEPS);
    const float* base = x + ((long)(b * TSTEPS + t) * CIN) * NPIX + p;
    float v[CIN];
    float s = 0.f;
    #pragma unroll
    for (int c = 0; c < CIN; c++) { v[c] = base[c * NPIX]; s += v[c]; }
    float mu = s * (1.f / CIN);
    float q = 0.f;
    #pragma unroll
    for (int c = 0; c < CIN; c++) { float d = v[c] - mu; q += d * d; }
    float rs = rsqrtf(q * (1.f / CIN) + 1e-5f);
    float* ob = xn + ((long)(t * BATCH + b) * CIN) * NPIX + p;
    #pragma unroll
    for (int c = 0; c < CIN; c++) ob[c * NPIX] = (v[c] - mu) * rs * gamma[c] + beta[c];
}

// weight prep: fp32 [Cout][Ktot] -> hi/lo bf16 [Cout][Kpad], optional gate permutation.
// perm: GEMM channel o takes original channel ((o>>3)&3)*64 + (o>>5)*8 + (o&7)
// so that gates (i,f,o,g) of one hidden unit land in one thread's accumulators.
__global__ void wprep_kernel(const float* __restrict__ W,
                             __nv_bfloat16* __restrict__ hi,
                             __nv_bfloat16* __restrict__ lo,
                             int Cout, int Ktot, int Kpad, int perm) {
    int i = blockIdx.x * blockDim.x + threadIdx.x;
    if (i >= Cout * Kpad) return;
    int o = i / Kpad, k = i - o * Kpad;
    int orig = perm ? (((o >> 3) & 3) * 64 + (o >> 5) * 8 + (o & 7)) : o;
    float v = (k < Ktot) ? W[(long)orig * Ktot + k] : 0.f;
    __nv_bfloat16 h = __float2bfloat16(v);
    hi[i] = h;
    lo[i] = __float2bfloat16(v - __bfloat162float(h));
}

// ---------------- mma.sync implicit-GEMM conv (+fused epilogue) ----------------
// CTA tile: M=128 pixels (image blockIdx.y, pixel block blockIdx.x) x NCH channels.
// Warp grid: 2 (M, tile 64) x NWN (N, tile NTILE). bf16 3-way split, fp32 acc.
// EPI=0: LSTM gates fused epilogue (perm'd weights), EPI=1: bias+relu.
template<int NTILE, int NWN, int EPI>
__global__ __launch_bounds__(NWN * 64, 1)
void convmma_kernel(const float* __restrict__ in0, int C0,
                    const float* __restrict__ in1, int C1,
                    const __nv_bfloat16* __restrict__ Whi,
                    const __nv_bfloat16* __restrict__ Wlo,
                    int Ktot, int Kpad,
                    const float* __restrict__ bias,
                    float* __restrict__ out_h, float* __restrict__ out_c) {
    constexpr int NTH = NWN * 64;           // threads
    constexpr int NCH = NWN * NTILE;        // total channels
    constexpr int NFRAG = NTILE / 8;
    constexpr int NF2 = NTILE / 16;
    constexpr int LDA = 80;                 // bytes per smem row (32 halves + 8 pad)
    constexpr int APLANE = 128 * LDA;
    constexpr int BPLANE = NCH * LDA;
    constexpr int BUF = 2 * APLANE + 2 * BPLANE;

    extern __shared__ char smem[];
    const uint32_t sb = smem_u32(smem);
    const int tid = threadIdx.x;
    const int l = tid & 31;
    const int wid = tid >> 5;
    const int wm = wid & 1;
    const int wn = wid >> 1;
    const int img = blockIdx.y;
    const int pix0 = blockIdx.x * 128;

    // per-thread gather geometry (row fixed per thread)
    const int arow = tid & 127;
    const int ap = pix0 + arow;
    const int apy = ap / SP;
    const int apx = ap - apy * SP;
    const bool apv = ap < NPIX;
    constexpr int AE = 4096 / NTH;          // A elems per thread per stage
    constexpr int KSTEP = NTH >> 7;         // k stride per e

    const int nstage = Kpad >> 5;

    float acc[4][NFRAG][4];
    #pragma unroll
    for (int a = 0; a < 4; a++)
        #pragma unroll
        for (int b = 0; b < NFRAG; b++)
            #pragma unroll
            for (int c = 0; c < 4; c++) acc[a][b][c] = 0.f;

    // ---- gather one K-stage into buffer ----
    auto gather = [&](int s, char* buf) {
        const int k0 = s << 5;
        #pragma unroll
        for (int e = 0; e < AE; e++) {
            int k = (tid >> 7) + e * KSTEP;
            int kabs = k0 + k;
            float v = 0.f;
            if (kabs < Ktot && apv) {
                int cc = kabs / 9;
                int r = kabs - cc * 9;
                int ky = r / 3, kx = r - ky * 3;
                int iy = apy + ky - 1, ix = apx + kx - 1;
                if ((unsigned)iy < (unsigned)SP && (unsigned)ix < (unsigned)SP) {
                    const float* pl = (cc < C0)
                        ? in0 + ((long)img * C0 + cc) * NPIX
                        : in1 + ((long)img * C1 + (cc - C0)) * NPIX;
                    v = __ldg(pl + iy * SP + ix);
                }
            }
            __nv_bfloat16 hb = __float2bfloat16(v);
            __nv_bfloat16 lb = __float2bfloat16(v - __bfloat162float(hb));
            int off = arow * LDA + k * 2;
            *(unsigned short*)(buf + off) = *(unsigned short*)&hb;
            *(unsigned short*)(buf + APLANE + off) = *(unsigned short*)&lb;
        }
        const __nv_bfloat16* wh = Whi + k0;
        const __nv_bfloat16* wl = Wlo + k0;
        for (int i = tid; i < NCH * 4; i += NTH) {
            int n = i >> 2, j = i & 3;
            uint4 vh = *(const uint4*)(wh + (long)n * Kpad + j * 8);
            uint4 vl = *(const uint4*)(wl + (long)n * Kpad + j * 8);
            int off = n * LDA + j * 16;
            *(uint4*)(buf + 2 * APLANE + off) = vh;
            *(uint4*)(buf + 2 * APLANE + BPLANE + off) = vl;
        }
    };

    gather(0, smem);
    __syncthreads();

    for (int s = 0; s < nstage; s++) {
        if (s + 1 < nstage) gather(s + 1, smem + ((s + 1) & 1) * BUF);

        const uint32_t cur = sb + (s & 1) * BUF;
        const uint32_t sAh = cur, sAl = cur + APLANE;
        const uint32_t sBh = cur + 2 * APLANE, sBl = sBh + BPLANE;

        #pragma unroll
        for (int h = 0; h < 2; h++) {
            uint32_t bh[NF2][4], bl[NF2][4];
            const int brow = wn * NTILE + ((l >> 4) & 1) * 8 + (l & 7);
            const int bko = h * 16 + ((l >> 3) & 1) * 8;
            #pragma unroll
            for (int nf2 = 0; nf2 < NF2; nf2++) {
                LDSM4(bh[nf2], sBh + (brow + nf2 * 16) * LDA + bko * 2);
                LDSM4(bl[nf2], sBl + (brow + nf2 * 16) * LDA + bko * 2);
            }
            const int aro = wm * 64 + (l & 15);
            const int ako = h * 16 + (l >> 4) * 8;
            #pragma unroll
            for (int mf = 0; mf < 4; mf++) {
                uint32_t ah[4], al[4];
                LDSM4(ah, sAh + (aro + mf * 16) * LDA + ako * 2);
                LDSM4(al, sAl + (aro + mf * 16) * LDA + ako * 2);
                #pragma unroll
                for (int nf = 0; nf < NFRAG; nf++) {
                    const uint32_t* bhp = &bh[nf >> 1][(nf & 1) * 2];
                    const uint32_t* blp = &bl[nf >> 1][(nf & 1) * 2];
                    mma_bf16(acc[mf][nf], ah, bhp);
                    mma_bf16(acc[mf][nf], ah, blp);
                    mma_bf16(acc[mf][nf], al, bhp);
                }
            }
        }
        __syncthreads();
    }

    // ---- epilogue ----
    if (EPI == 0) {
        #pragma unroll
        for (int mf = 0; mf < 4; mf++) {
            int pbase = pix0 + wm * 64 + mf * 16 + (l >> 2);
            #pragma unroll
            for (int c = 0; c < 4; c++) {
                int p = pbase + ((c >> 1) & 1) * 8;
                #pragma unroll
                for (int g2 = 0; g2 < NTILE / 32; g2++) {
                    int j = wn * (NTILE / 4) + g2 * 8 + (l & 3) * 2 + (c & 1);
                    float zi = acc[mf][g2 * 4 + 0][c] + __ldg(bias + j);
                    float zf = acc[mf][g2 * 4 + 1][c] + __ldg(bias + 64 + j);
                    float zo = acc[mf][g2 * 4 + 2][c] + __ldg(bias + 128 + j);
                    float zg = acc[mf][g2 * 4 + 3][c] + __ldg(bias + 192 + j);
                    if (p < NPIX) {
                        long idx = ((long)img * HID + j) * NPIX + p;
                        float ig = sigm(zi), fg = sigm(zf), og = sigm(zo);
                        float gg = tanh_acc(zg);
                        float cn = fg * out_c[idx] + ig * gg;
                        out_c[idx] = cn;
                        out_h[idx] = og * tanh_acc(cn);
                    }
                }
            }
        }
    } else {
        #pragma unroll
        for (int mf = 0; mf < 4; mf++) {
            int pbase = pix0 + wm * 64 + mf * 16 + (l >> 2);
            #pragma unroll
            for (int c = 0; c < 4; c++) {
                int p = pbase + ((c >> 1) & 1) * 8;
                #pragma unroll
                for (int nf = 0; nf < NFRAG; nf++) {
                    int n = wn * NTILE + nf * 8 + (l & 3) * 2 + (c & 1);
                    float v = acc[mf][nf][c] + __ldg(bias + n);
                    if (p < NPIX)
                        out_h[((long)img * HID + n) * NPIX + p] = fmaxf(v, 0.f);
                }
            }
        }
    }
}

// ---------------- maxpool 2x2 stride 2 ----------------
__global__ void pool_kernel(const float* __restrict__ y, float* __restrict__ out) {
    int idx = blockIdx.x * blockDim.x + threadIdx.x;
    if (idx >= BATCH * HID * POOLD * POOLD) return;
    int j = idx % POOLD;
    int i = (idx / POOLD) % POOLD;
    int ch = (idx / (POOLD * POOLD)) % HID;
    int b = idx / (POOLD * POOLD * HID);
    const float* p = y + ((long)(b * HID + ch)) * NPIX + (2 * i) * SP + 2 * j;
    float m = fmaxf(fmaxf(p[0], p[1]), fmaxf(p[SP], p[SP + 1]));
    out[(long)b * FEAT + ch * (POOLD * POOLD) + i * POOLD + j] = m;
}

// ---------------- FC: one warp per output element ----------------
__global__ void fc_kernel(const float* __restrict__ in, const float* __restrict__ w,
                          const float* __restrict__ b, float* __restrict__ out,
                          int M, int N, int K, int relu) {
    int warp = (blockIdx.x * blockDim.x + threadIdx.x) >> 5;
    int lane = threadIdx.x & 31;
    if (warp >= M * N) return;
    int m = warp / N, n = warp - m * N;
    const float* ir = in + (long)m * K;
    const float* wr = w + (long)n * K;
    float s = 0.f;
    for (int k = lane; k < K; k += 32) s += ir[k] * wr[k];
    #pragma unroll
    for (int o = 16; o; o >>= 1) s += __shfl_xor_sync(0xFFFFFFFFu, s, o);
    if (lane == 0) {
        s += b[n];
        if (relu) s = fmaxf(s, 0.f);
        out[(long)m * N + n] = s;
    }
}

__global__ void lsm_kernel(const float* __restrict__ in, float* __restrict__ out) {
    int m = blockIdx.x * blockDim.x + threadIdx.x;
    if (m >= BATCH) return;
    float a = in[2 * m], b = in[2 * m + 1];
    float mx = fmaxf(a, b);
    float l = mx + logf(expf(a - mx) + expf(b - mx));
    out[2 * m] = a - l;
    out[2 * m + 1] = b - l;
}

// ---------------- launch ----------------
extern "C" void kernel_launch(void* const* d_in, const int* in_sizes, int n_in,
                              void* d_out, int out_size) {
    const float* x   = (const float*)d_in[0];
    const float* lg  = (const float*)d_in[1];
    const float* lb  = (const float*)d_in[2];
    const float* w0  = (const float*)d_in[3];
    const float* b0  = (const float*)d_in[4];
    const float* w1  = (const float*)d_in[5];
    const float* b1  = (const float*)d_in[6];
    const float* wc  = (const float*)d_in[7];
    const float* bc  = (const float*)d_in[8];
    const float* wf1 = (const float*)d_in[9];
    const float* bf1 = (const float*)d_in[10];
    const float* wf2 = (const float*)d_in[11];
    const float* bf2 = (const float*)d_in[12];
    const float* wf3 = (const float*)d_in[13];
    const float* bf3 = (const float*)d_in[14];
    float* out = (float*)d_out;

    float *xn, *h0a, *h0b, *h1a, *h1b, *c0, *c1, *y, *pool, *f1, *f2, *f3;
    __nv_bfloat16 *w0h, *w0l, *w1h, *w1l, *wch, *wcl;
    cudaGetSymbolAddress((void**)&xn,  g_xn);
    cudaGetSymbolAddress((void**)&h0a, g_h0a);
    cudaGetSymbolAddress((void**)&h0b, g_h0b);
    cudaGetSymbolAddress((void**)&h1a, g_h1a);
    cudaGetSymbolAddress((void**)&h1b, g_h1b);
    cudaGetSymbolAddress((void**)&c0,  g_c0);
    cudaGetSymbolAddress((void**)&c1,  g_c1);
    cudaGetSymbolAddress((void**)&y,   g_y);
    cudaGetSymbolAddress((void**)&pool, g_pool);
    cudaGetSymbolAddress((void**)&f1, g_f1);
    cudaGetSymbolAddress((void**)&f2, g_f2);
    cudaGetSymbolAddress((void**)&f3, g_f3);
    cudaGetSymbolAddress((void**)&w0h, g_w0h);
    cudaGetSymbolAddress((void**)&w0l, g_w0l);
    cudaGetSymbolAddress((void**)&w1h, g_w1h);
    cudaGetSymbolAddress((void**)&w1l, g_w1l);
    cudaGetSymbolAddress((void**)&wch, g_wch);
    cudaGetSymbolAddress((void**)&wcl, g_wcl);

    // smem: double-buffered (A hi/lo 128x80B) + (B hi/lo NCHx80B)
    const int SMEM0 = 2 * (2 * 128 * 80 + 2 * 256 * 80);  // 122880
    const int SMEM1 = 2 * (2 * 128 * 80 + 2 * 64 * 80);   // 61440
    cudaFuncSetAttribute(convmma_kernel<64, 4, 0>, cudaFuncAttributeMaxDynamicSharedMemorySize, SMEM0);
    cudaFuncSetAttribute(convmma_kernel<32, 2, 1>, cudaFuncAttributeMaxDynamicSharedMemorySize, SMEM1);

    const int nstate = BATCH * HID * NPIX;
    zero_state_kernel<<<(nstate + 255) / 256, 256>>>(h0a, c0, h1a, c1, nstate);

    const int nln = BATCH * TSTEPS * NPIX;
    ln_kernel<<<(nln + 255) / 256, 256>>>(x, lg, lb, xn);

    wprep_kernel<<<(GATES * K0PAD + 255) / 256, 256>>>(w0, w0h, w0l, GATES, K0TOT, K0PAD, 1);
    wprep_kernel<<<(GATES * K1PAD + 255) / 256, 256>>>(w1, w1h, w1l, GATES, K1TOT, K1PAD, 1);
    wprep_kernel<<<(HID * KCPAD + 255) / 256, 256>>>(wc, wch, wcl, HID, KCTOT, KCPAD, 0);

    float* h0buf[2] = {h0a, h0b};
    float* h1buf[2] = {h1a, h1b};
    dim3 grid(5, BATCH);
    for (int t = 0; t < TSTEPS; t++) {
        int r = t & 1;
        const float* xt = xn + (long)t * BATCH * CIN * NPIX;
        convmma_kernel<64, 4, 0><<<grid, 256, SMEM0>>>(
            xt, CIN, h0buf[r], HID, w0h, w0l, K0TOT, K0PAD, b0, h0buf[1 - r], c0);
        convmma_kernel<64, 4, 0><<<grid, 256, SMEM0>>>(
            h0buf[1 - r], HID, h1buf[r], HID, w1h, w1l, K1TOT, K1PAD, b1, h1buf[1 - r], c1);
    }
    const float* hfin = h1buf[TSTEPS & 1 ? 0 : 1];  // last write went to 1-(T-1)&1
    // T=20: last t=19, r=1, wrote h1buf[0]
    hfin = h1buf[(TSTEPS - 1) & 1 ? 0 : 1];

    convmma_kernel<32, 2, 1><<<grid, 128, SMEM1>>>(
        hfin, HID, (const float*)0, 0, wch, wcl, KCTOT, KCPAD, bc, y, (float*)0);

    const int npool = BATCH * HID * POOLD * POOLD;
    pool_kernel<<<(npool + 255) / 256, 256>>>(y, pool);
    {
        int warps = BATCH * FC1N;
        fc_kernel<<<(warps * 32 + 255) / 256, 256>>>(pool, wf1, bf1, f1, BATCH, FC1N, FEAT, 1);
    }
    {
        int warps = BATCH * FC2N;
        fc_kernel<<<(warps * 32 + 255) / 256, 256>>>(f1, wf2, bf2, f2, BATCH, FC2N, FC1N, 1);
    }
    {
        int warps = BATCH * 2;
        fc_kernel<<<(warps * 32 + 255) / 256, 256>>>(f2, wf3, bf3, f3, BATCH, 2, FC2N, 0);
    }
    lsm_kernel<<<1, BATCH>>>(f3, out);
}

// round 4
// speedup vs baseline: 1.9135x; 1.2637x over previous
#include <cuda_runtime.h>
#include <cuda_bf16.h>
#include <math.h>
#include <cstdint>

// ---------------- problem constants ----------------
#define BATCH 64
#define TSTEPS 20
#define CIN 25
#define HID 64
#define SP 25
#define NPIX 625
#define GATES 256
#define POOLD 12
#define FEAT 9216
#define FC1N 128
#define FC2N 64

#define K0TOT ((CIN + HID) * 9)   // 801
#define K0PAD 832                 // 26 stages of 32
#define K1TOT (2 * HID * 9)       // 1152
#define K1PAD 1152                // 36 stages
#define KCTOT (HID * 9)           // 576
#define KCPAD 576                 // 18 stages

// ---------------- scratch (device globals, no allocation) ----------------
// packed activations: u32 = (bf16 hi << 16) | bf16 lo
__device__ __align__(16) uint32_t g_xn[(long)TSTEPS * BATCH * CIN * NPIX];
__device__ __align__(16) uint32_t g_h0a[(long)BATCH * HID * NPIX];
__device__ __align__(16) uint32_t g_h0b[(long)BATCH * HID * NPIX];
__device__ __align__(16) uint32_t g_h1a[(long)BATCH * HID * NPIX];
__device__ __align__(16) uint32_t g_h1b[(long)BATCH * HID * NPIX];
// c: pixel-major [img][pix][64]
__device__ __align__(16) float g_c0[(long)BATCH * NPIX * HID];
__device__ __align__(16) float g_c1[(long)BATCH * NPIX * HID];
__device__ __align__(16) float g_y [(long)BATCH * HID * NPIX];
__device__ __align__(16) float g_pool[(long)BATCH * FEAT];
__device__ float g_f1[BATCH * FC1N];
__device__ float g_f2[BATCH * FC2N];
__device__ float g_f3[BATCH * 2];
__device__ __align__(16) __nv_bfloat16 g_w0h[GATES * K0PAD];
__device__ __align__(16) __nv_bfloat16 g_w0l[GATES * K0PAD];
__device__ __align__(16) __nv_bfloat16 g_w1h[GATES * K1PAD];
__device__ __align__(16) __nv_bfloat16 g_w1l[GATES * K1PAD];
__device__ __align__(16) __nv_bfloat16 g_wch[HID * KCPAD];
__device__ __align__(16) __nv_bfloat16 g_wcl[HID * KCPAD];

// ---------------- helpers ----------------
__device__ __forceinline__ uint32_t smem_u32(const void* p) {
    uint32_t a;
    asm("{ .reg .u64 t; cvta.to.shared.u64 t, %1; cvt.u32.u64 %0, t; }" : "=r"(a) : "l"(p));
    return a;
}
#define LDSM4(r, a) \
    asm volatile("ldmatrix.sync.aligned.m8n8.x4.shared.b16 {%0,%1,%2,%3}, [%4];" \
        : "=r"((r)[0]), "=r"((r)[1]), "=r"((r)[2]), "=r"((r)[3]) : "r"(a))

__device__ __forceinline__ void mma_bf16(float* c, const uint32_t* a, const uint32_t* b) {
    asm volatile(
        "mma.sync.aligned.m16n8k16.row.col.f32.bf16.bf16.f32 "
        "{%0,%1,%2,%3}, {%4,%5,%6,%7}, {%8,%9}, {%0,%1,%2,%3};"
        : "+f"(c[0]), "+f"(c[1]), "+f"(c[2]), "+f"(c[3])
        : "r"(a[0]), "r"(a[1]), "r"(a[2]), "r"(a[3]), "r"(b[0]), "r"(b[1]));
}

__device__ __forceinline__ float sigm(float x) { return 1.f / (1.f + __expf(-x)); }
__device__ __forceinline__ float tanh_acc(float x) {
    float e = __expf(-2.f * fabsf(x));
    float t = (1.f - e) / (1.f + e);
    return copysignf(t, x);
}
__device__ __forceinline__ uint32_t pack_hl(float v) {
    __nv_bfloat16 h = __float2bfloat16(v);
    float hf = __bfloat162float(h);
    __nv_bfloat16 lo = __float2bfloat16(v - hf);
    return ((uint32_t)__bfloat16_as_ushort(h) << 16) | (uint32_t)__bfloat16_as_ushort(lo);
}
// smem swizzle for 64B rows: XOR byte bits[4:5] with row bits[1:2]
__device__ __forceinline__ int swz(int row, int kbyte) {
    return row * 64 + (kbyte ^ (((row >> 1) & 3) << 4));
}

// ---------------- small kernels ----------------
__global__ void zero_state_kernel(uint32_t* a, float* b, uint32_t* c, float* d, int n) {
    int i = blockIdx.x * blockDim.x + threadIdx.x;
    if (i < n) { a[i] = 0u; b[i] = 0.f; c[i] = 0u; d[i] = 0.f; }
}

__global__ void ln_kernel(const float* __restrict__ x,
                          const float* __restrict__ gamma,
                          const float* __restrict__ beta,
                          uint32_t* __restrict__ xn) {
    int idx = blockIdx.x * blockDim.x + threadIdx.x;
    if (idx >= BATCH * TSTEPS * NPIX) return;
    int p = idx % NPIX;
    int t = (idx / NPIX) % TSTEPS;
    int b = idx / (NPIX * TSTEPS);
    const float* base = x + ((long)(b * TSTEPS + t) * CIN) * NPIX + p;
    float v[CIN];
    float s = 0.f;
    #pragma unroll
    for (int c = 0; c < CIN; c++) { v[c] = base[c * NPIX]; s += v[c]; }
    float mu = s * (1.f / CIN);
    float q = 0.f;
    #pragma unroll
    for (int c = 0; c < CIN; c++) { float d = v[c] - mu; q += d * d; }
    float rs = rsqrtf(q * (1.f / CIN) + 1e-5f);
    uint32_t* ob = xn + ((long)(t * BATCH + b) * CIN) * NPIX + p;
    #pragma unroll
    for (int c = 0; c < CIN; c++) ob[c * NPIX] = pack_hl((v[c] - mu) * rs * gamma[c] + beta[c]);
}

// weight prep: fp32 [Cout][Ktot] -> hi/lo bf16 [Cout][Kpad] in GEMM order.
// perm=1 (LSTM): GEMM row o -> orig channel nf*64 + nblk*32 + wn*8 + r
//   where r=o&7, nf=(o>>3)&3, wn=(o>>5)&3, nblk=(o>>7)&1.
__global__ void wprep_kernel(const float* __restrict__ W,
                             __nv_bfloat16* __restrict__ hi,
                             __nv_bfloat16* __restrict__ lo,
                             int Cout, int Ktot, int Kpad, int perm) {
    int i = blockIdx.x * blockDim.x + threadIdx.x;
    if (i >= Cout * Kpad) return;
    int o = i / Kpad, k = i - o * Kpad;
    int orig = perm ? (((o >> 3) & 3) * 64 + ((o >> 7) & 1) * 32 + ((o >> 5) & 3) * 8 + (o & 7)) : o;
    float v = (k < Ktot) ? W[(long)orig * Ktot + k] : 0.f;
    __nv_bfloat16 h = __float2bfloat16(v);
    hi[i] = h;
    lo[i] = __float2bfloat16(v - __bfloat162float(h));
}

// ---------------- mma.sync implicit-GEMM conv (+fused epilogue) ----------------
// CTA: M=128 pixels x NCH=NWN*32 channels, warp tile 64x32, bf16 3-way split.
// EPI=0: fused LSTM gates, h packed u32 plane-major out, c fp32 pixel-major in/out,
//        smem-staged coalesced IO. blockIdx.z = N-block (2 blocks of 128 GEMM ch).
// EPI=1: bias+relu, fp32 plane-major out (direct epilogue).
template<int NWN, int EPI>
__global__ __launch_bounds__(NWN * 64, 2)
void convmma_kernel(const uint32_t* __restrict__ in0, int C0,
                    const uint32_t* __restrict__ in1, int C1,
                    const __nv_bfloat16* __restrict__ Whi,
                    const __nv_bfloat16* __restrict__ Wlo,
                    int Ktot, int Kpad,
                    const float* __restrict__ bias,
                    void* __restrict__ out_h_, float* __restrict__ out_c) {
    constexpr int NTH = NWN * 64;
    constexpr int NCH = NWN * 32;
    constexpr int APLANE = 128 * 64;
    constexpr int BPLANE = NCH * 64;
    constexpr int BUF = 2 * APLANE + 2 * BPLANE;
    constexpr int AE = 4096 / NTH;
    constexpr int KSTEP = NTH >> 7;

    extern __shared__ char smem[];
    const uint32_t sb = smem_u32(smem);
    float* cs = (float*)(smem + 2 * BUF);            // [128][36] fp32 (EPI0)
    uint32_t* hs = (uint32_t*)(smem + 2 * BUF + 128 * 36 * 4);  // [128][33] packed

    const int tid = threadIdx.x;
    const int l = tid & 31;
    const int wid = tid >> 5;
    const int wm = wid & 1;
    const int wn = wid >> 1;
    const int img = blockIdx.y;
    const int pix0 = blockIdx.x * 128;
    const int nblk = blockIdx.z;
    const int nbase = nblk * NCH;

    const int arow = tid & 127;
    const int ap = pix0 + arow;
    const int apy = ap / SP;
    const int apx = ap - apy * SP;
    const bool apv = ap < NPIX;

    const int nstage = Kpad >> 5;

    float acc[4][4][4];
    #pragma unroll
    for (int a = 0; a < 4; a++)
        #pragma unroll
        for (int b = 0; b < 4; b++)
            #pragma unroll
            for (int c = 0; c < 4; c++) acc[a][b][c] = 0.f;

    auto gather = [&](int s, int bi) {
        char* buf = smem + bi * BUF;
        const int k0 = s << 5;
        #pragma unroll
        for (int e = 0; e < AE; e++) {
            int k = (KSTEP == 2) ? ((tid >> 7) + e * 2) : e;
            int kabs = k0 + k;
            uint32_t w = 0;
            if (kabs < Ktot && apv) {
                int cc = kabs / 9;
                int r = kabs - cc * 9;
                int ky = r / 3, kx = r - ky * 3;
                int iy = apy + ky - 1, ix = apx + kx - 1;
                if ((unsigned)iy < (unsigned)SP && (unsigned)ix < (unsigned)SP) {
                    const uint32_t* pl = (cc < C0)
                        ? in0 + ((long)img * C0 + cc) * NPIX
                        : in1 + ((long)img * C1 + (cc - C0)) * NPIX;
                    w = __ldg(pl + iy * SP + ix);
                }
            }
            int off = swz(arow, k * 2);
            *(uint16_t*)(buf + off) = (uint16_t)(w >> 16);
            *(uint16_t*)(buf + APLANE + off) = (uint16_t)(w & 0xffffu);
        }
        const __nv_bfloat16* wh = Whi + k0;
        const __nv_bfloat16* wl = Wlo + k0;
        #pragma unroll
        for (int i = tid; i < NCH * 4; i += NTH) {
            int n = i >> 2, j = i & 3;
            long wr = (long)(nbase + n) * Kpad + j * 8;
            uint4 vh = *(const uint4*)(wh + wr);
            uint4 vl = *(const uint4*)(wl + wr);
            int off = swz(n, j * 16);
            *(uint4*)(buf + 2 * APLANE + off) = vh;
            *(uint4*)(buf + 2 * APLANE + BPLANE + off) = vl;
        }
    };

    gather(0, 0);

    // cooperative coalesced load of old c into staging (EPI0)
    if (EPI == 0) {
        #pragma unroll
        for (int i = 0; i < 1024 / NTH; i++) {
            int idx4 = tid + i * NTH;
            int p = idx4 >> 3, jq = idx4 & 7;
            int pg = pix0 + p;
            float4 v = make_float4(0.f, 0.f, 0.f, 0.f);
            if (pg < NPIX)
                v = *(const float4*)(out_c + ((long)img * NPIX + pg) * 64 + nblk * 32 + jq * 4);
            *(float4*)(cs + p * 36 + jq * 4) = v;
        }
    }
    __syncthreads();

    for (int s = 0; s < nstage; s++) {
        if (s + 1 < nstage) gather(s + 1, (s + 1) & 1);

        const uint32_t cur = sb + (s & 1) * BUF;
        const uint32_t sAh = cur, sAl = cur + APLANE;
        const uint32_t sBh = cur + 2 * APLANE, sBl = sBh + BPLANE;

        #pragma unroll
        for (int h = 0; h < 2; h++) {
            uint32_t bh[2][4], bl[2][4];
            const int brow = wn * 32 + ((l >> 4) & 1) * 8 + (l & 7);
            const int bko = (h * 16 + ((l >> 3) & 1) * 8) * 2;
            #pragma unroll
            for (int nf2 = 0; nf2 < 2; nf2++) {
                LDSM4(bh[nf2], sBh + swz(brow + nf2 * 16, bko));
                LDSM4(bl[nf2], sBl + swz(brow + nf2 * 16, bko));
            }
            const int aro = wm * 64 + (l & 15);
            const int ako = (h * 16 + (l >> 4) * 8) * 2;
            #pragma unroll
            for (int mf = 0; mf < 4; mf++) {
                uint32_t ah[4], al[4];
                LDSM4(ah, sAh + swz(aro + mf * 16, ako));
                LDSM4(al, sAl + swz(aro + mf * 16, ako));
                #pragma unroll
                for (int nf = 0; nf < 4; nf++) {
                    const uint32_t* bhp = &bh[nf >> 1][(nf & 1) * 2];
                    const uint32_t* blp = &bl[nf >> 1][(nf & 1) * 2];
                    mma_bf16(acc[mf][nf], ah, bhp);
                    mma_bf16(acc[mf][nf], ah, blp);
                    mma_bf16(acc[mf][nf], al, bhp);
                }
            }
        }
        __syncthreads();
    }

    if (EPI == 0) {
        // fused gates into staging
        #pragma unroll
        for (int mf = 0; mf < 4; mf++) {
            int pb = wm * 64 + mf * 16 + (l >> 2);
            #pragma unroll
            for (int c = 0; c < 4; c++) {
                int p = pb + ((c >> 1) & 1) * 8;
                int j = wn * 8 + (l & 3) * 2 + (c & 1);
                int u = nblk * 32 + j;
                float zi = acc[mf][0][c] + __ldg(bias + u);
                float zf = acc[mf][1][c] + __ldg(bias + 64 + u);
                float zo = acc[mf][2][c] + __ldg(bias + 128 + u);
                float zg = acc[mf][3][c] + __ldg(bias + 192 + u);
                if (pix0 + p < NPIX) {
                    float ig = sigm(zi), fg = sigm(zf), og = sigm(zo);
                    float gg = tanh_acc(zg);
                    float cn = fg * cs[p * 36 + j] + ig * gg;
                    cs[p * 36 + j] = cn;
                    hs[p * 33 + j] = pack_hl(og * tanh_acc(cn));
                }
            }
        }
        __syncthreads();
        // coalesced store: c (pixel-major float4)
        uint32_t* out_h = (uint32_t*)out_h_;
        #pragma unroll
        for (int i = 0; i < 1024 / NTH; i++) {
            int idx4 = tid + i * NTH;
            int p = idx4 >> 3, jq = idx4 & 7;
            int pg = pix0 + p;
            if (pg < NPIX)
                *(float4*)(out_c + ((long)img * NPIX + pg) * 64 + nblk * 32 + jq * 4) =
                    *(const float4*)(cs + p * 36 + jq * 4);
        }
        // coalesced store: h planes (packed u32, 128-px runs)
        #pragma unroll
        for (int uu = 0; uu < 32 * 32 / NTH; uu++) {
            int unit = (tid >> 5) + uu * (NTH / 32);
            #pragma unroll
            for (int i = 0; i < 4; i++) {
                int px = i * 32 + l;
                int pg = pix0 + px;
                if (pg < NPIX)
                    out_h[((long)img * HID + nblk * 32 + unit) * NPIX + pg] = hs[px * 33 + unit];
            }
        }
    } else {
        float* out_h = (float*)out_h_;
        #pragma unroll
        for (int mf = 0; mf < 4; mf++) {
            int pbase = pix0 + wm * 64 + mf * 16 + (l >> 2);
            #pragma unroll
            for (int c = 0; c < 4; c++) {
                int p = pbase + ((c >> 1) & 1) * 8;
                #pragma unroll
                for (int nf = 0; nf < 4; nf++) {
                    int n = wn * 32 + nf * 8 + (l & 3) * 2 + (c & 1);
                    float v = acc[mf][nf][c] + __ldg(bias + n);
                    if (p < NPIX)
                        out_h[((long)img * HID + n) * NPIX + p] = fmaxf(v, 0.f);
                }
            }
        }
    }
}

// ---------------- maxpool 2x2 stride 2 ----------------
__global__ void pool_kernel(const float* __restrict__ y, float* __restrict__ out) {
    int idx = blockIdx.x * blockDim.x + threadIdx.x;
    if (idx >= BATCH * HID * POOLD * POOLD) return;
    int j = idx % POOLD;
    int i = (idx / POOLD) % POOLD;
    int ch = (idx / (POOLD * POOLD)) % HID;
    int b = idx / (POOLD * POOLD * HID);
    const float* p = y + ((long)(b * HID + ch)) * NPIX + (2 * i) * SP + 2 * j;
    float m = fmaxf(fmaxf(p[0], p[1]), fmaxf(p[SP], p[SP + 1]));
    out[(long)b * FEAT + ch * (POOLD * POOLD) + i * POOLD + j] = m;
}

// ---------------- FC: one warp per output element ----------------
__global__ void fc_kernel(const float* __restrict__ in, const float* __restrict__ w,
                          const float* __restrict__ b, float* __restrict__ out,
                          int M, int N, int K, int relu) {
    int warp = (blockIdx.x * blockDim.x + threadIdx.x) >> 5;
    int lane = threadIdx.x & 31;
    if (warp >= M * N) return;
    int m = warp / N, n = warp - m * N;
    const float* ir = in + (long)m * K;
    const float* wr = w + (long)n * K;
    float s = 0.f;
    for (int k = lane; k < K; k += 32) s += ir[k] * wr[k];
    #pragma unroll
    for (int o = 16; o; o >>= 1) s += __shfl_xor_sync(0xFFFFFFFFu, s, o);
    if (lane == 0) {
        s += b[n];
        if (relu) s = fmaxf(s, 0.f);
        out[(long)m * N + n] = s;
    }
}

__global__ void lsm_kernel(const float* __restrict__ in, float* __restrict__ out) {
    int m = blockIdx.x * blockDim.x + threadIdx.x;
    if (m >= BATCH) return;
    float a = in[2 * m], b = in[2 * m + 1];
    float mx = fmaxf(a, b);
    float l = mx + logf(expf(a - mx) + expf(b - mx));
    out[2 * m] = a - l;
    out[2 * m + 1] = b - l;
}

// ---------------- launch ----------------
extern "C" void kernel_launch(void* const* d_in, const int* in_sizes, int n_in,
                              void* d_out, int out_size) {
    const float* x   = (const float*)d_in[0];
    const float* lg  = (const float*)d_in[1];
    const float* lb  = (const float*)d_in[2];
    const float* w0  = (const float*)d_in[3];
    const float* b0  = (const float*)d_in[4];
    const float* w1  = (const float*)d_in[5];
    const float* b1  = (const float*)d_in[6];
    const float* wc  = (const float*)d_in[7];
    const float* bc  = (const float*)d_in[8];
    const float* wf1 = (const float*)d_in[9];
    const float* bf1 = (const float*)d_in[10];
    const float* wf2 = (const float*)d_in[11];
    const float* bf2 = (const float*)d_in[12];
    const float* wf3 = (const float*)d_in[13];
    const float* bf3 = (const float*)d_in[14];
    float* out = (float*)d_out;

    uint32_t *xn, *h0a, *h0b, *h1a, *h1b;
    float *c0, *c1, *y, *pool, *f1, *f2, *f3;
    __nv_bfloat16 *w0h, *w0l, *w1h, *w1l, *wch, *wcl;
    cudaGetSymbolAddress((void**)&xn,  g_xn);
    cudaGetSymbolAddress((void**)&h0a, g_h0a);
    cudaGetSymbolAddress((void**)&h0b, g_h0b);
    cudaGetSymbolAddress((void**)&h1a, g_h1a);
    cudaGetSymbolAddress((void**)&h1b, g_h1b);
    cudaGetSymbolAddress((void**)&c0,  g_c0);
    cudaGetSymbolAddress((void**)&c1,  g_c1);
    cudaGetSymbolAddress((void**)&y,   g_y);
    cudaGetSymbolAddress((void**)&pool, g_pool);
    cudaGetSymbolAddress((void**)&f1, g_f1);
    cudaGetSymbolAddress((void**)&f2, g_f2);
    cudaGetSymbolAddress((void**)&f3, g_f3);
    cudaGetSymbolAddress((void**)&w0h, g_w0h);
    cudaGetSymbolAddress((void**)&w0l, g_w0l);
    cudaGetSymbolAddress((void**)&w1h, g_w1h);
    cudaGetSymbolAddress((void**)&w1l, g_w1l);
    cudaGetSymbolAddress((void**)&wch, g_wch);
    cudaGetSymbolAddress((void**)&wcl, g_wcl);

    // smem sizes
    const int BUF0 = 2 * 128 * 64 + 2 * 128 * 64;           // 32768
    const int SMEM0 = 2 * BUF0 + 128 * 36 * 4 + 128 * 33 * 4; // 100864
    const int BUF1 = 2 * 128 * 64 + 2 * 64 * 64;            // 24576
    const int SMEM1 = 2 * BUF1;                             // 49152
    cudaFuncSetAttribute(convmma_kernel<4, 0>, cudaFuncAttributeMaxDynamicSharedMemorySize, SMEM0);
    cudaFuncSetAttribute(convmma_kernel<2, 1>, cudaFuncAttributeMaxDynamicSharedMemorySize, SMEM1);

    const int nstate = BATCH * HID * NPIX;
    zero_state_kernel<<<(nstate + 255) / 256, 256>>>(h0a, c0, h1a, c1, nstate);

    const int nln = BATCH * TSTEPS * NPIX;
    ln_kernel<<<(nln + 255) / 256, 256>>>(x, lg, lb, xn);

    wprep_kernel<<<(GATES * K0PAD + 255) / 256, 256>>>(w0, w0h, w0l, GATES, K0TOT, K0PAD, 1);
    wprep_kernel<<<(GATES * K1PAD + 255) / 256, 256>>>(w1, w1h, w1l, GATES, K1TOT, K1PAD, 1);
    wprep_kernel<<<(HID * KCPAD + 255) / 256, 256>>>(wc, wch, wcl, HID, KCTOT, KCPAD, 0);

    uint32_t* h0buf[2] = {h0a, h0b};
    uint32_t* h1buf[2] = {h1a, h1b};
    dim3 grid0(5, BATCH, 2);
    for (int t = 0; t < TSTEPS; t++) {
        int r = t & 1;
        const uint32_t* xt = xn + (long)t * BATCH * CIN * NPIX;
        convmma_kernel<4, 0><<<grid0, 256, SMEM0>>>(
            xt, CIN, h0buf[r], HID, w0h, w0l, K0TOT, K0PAD, b0, h0buf[1 - r], c0);
        convmma_kernel<4, 0><<<grid0, 256, SMEM0>>>(
            h0buf[1 - r], HID, h1buf[r], HID, w1h, w1l, K1TOT, K1PAD, b1, h1buf[1 - r], c1);
    }
    const uint32_t* hfin = h1buf[(TSTEPS - 1) & 1 ? 0 : 1];  // t=19 wrote h1buf[0]

    dim3 grid1(5, BATCH, 1);
    convmma_kernel<2, 1><<<grid1, 128, SMEM1>>>(
        hfin, HID, (const uint32_t*)0, 0, wch, wcl, KCTOT, KCPAD, bc, y, (float*)0);

    const int npool = BATCH * HID * POOLD * POOLD;
    pool_kernel<<<(npool + 255) / 256, 256>>>(y, pool);
    {
        int warps = BATCH * FC1N;
        fc_kernel<<<(warps * 32 + 255) / 256, 256>>>(pool, wf1, bf1, f1, BATCH, FC1N, FEAT, 1);
    }
    {
        int warps = BATCH * FC2N;
        fc_kernel<<<(warps * 32 + 255) / 256, 256>>>(f1, wf2, bf2, f2, BATCH, FC2N, FC1N, 1);
    }
    {
        int warps = BATCH * 2;
        fc_kernel<<<(warps * 32 + 255) / 256, 256>>>(f2, wf3, bf3, f3, BATCH, 2, FC2N, 0);
    }
    lsm_kernel<<<1, BATCH>>>(f3, out);
}

// round 5
// speedup vs baseline: 2.8891x; 1.5098x over previous
#include <cuda_runtime.h>
#include <cuda_bf16.h>
#include <math.h>
#include <cstdint>

// ---------------- problem constants ----------------
#define BATCH 64
#define TSTEPS 20
#define CIN 25
#define HID 64
#define SP 25
#define NPIX 625
#define GATES 256
#define POOLD 12
#define FEAT 9216
#define FC1N 128
#define FC2N 64

#define K0TOT ((CIN + HID) * 9)   // 801
#define K0PAD 832                 // 26 stages of 32
#define K1TOT (2 * HID * 9)       // 1152
#define K1PAD 1152                // 36 stages
#define KCTOT (HID * 9)           // 576
#define KCPAD 576                 // 18 stages

// ---------------- scratch (device globals, no allocation) ----------------
__device__ __align__(16) uint32_t g_xn[(long)TSTEPS * BATCH * CIN * NPIX];
__device__ __align__(16) uint32_t g_h0a[(long)BATCH * HID * NPIX];
__device__ __align__(16) uint32_t g_h0b[(long)BATCH * HID * NPIX];
__device__ __align__(16) uint32_t g_h1a[(long)BATCH * HID * NPIX];
__device__ __align__(16) uint32_t g_h1b[(long)BATCH * HID * NPIX];
__device__ __align__(16) float g_c0[(long)BATCH * NPIX * HID];
__device__ __align__(16) float g_c1[(long)BATCH * NPIX * HID];
__device__ __align__(16) float g_y [(long)BATCH * HID * NPIX];
__device__ __align__(16) float g_pool[(long)BATCH * FEAT];
__device__ float g_f1[BATCH * FC1N];
__device__ float g_f2[BATCH * FC2N];
__device__ float g_f3[BATCH * 2];
__device__ __align__(16) __nv_bfloat16 g_w0h[GATES * K0PAD];
__device__ __align__(16) __nv_bfloat16 g_w0l[GATES * K0PAD];
__device__ __align__(16) __nv_bfloat16 g_w1h[GATES * K1PAD];
__device__ __align__(16) __nv_bfloat16 g_w1l[GATES * K1PAD];
__device__ __align__(16) __nv_bfloat16 g_wch[HID * KCPAD];
__device__ __align__(16) __nv_bfloat16 g_wcl[HID * KCPAD];
__device__ __align__(16) int4 g_tap0[K0PAD];
__device__ __align__(16) int4 g_tap1[K1PAD];
__device__ __align__(16) int4 g_tapc[KCPAD];

// ---------------- helpers ----------------
__device__ __forceinline__ uint32_t smem_u32(const void* p) {
    uint32_t a;
    asm("{ .reg .u64 t; cvta.to.shared.u64 t, %1; cvt.u32.u64 %0, t; }" : "=r"(a) : "l"(p));
    return a;
}
#define LDSM4(r, a) \
    asm volatile("ldmatrix.sync.aligned.m8n8.x4.shared.b16 {%0,%1,%2,%3}, [%4];" \
        : "=r"((r)[0]), "=r"((r)[1]), "=r"((r)[2]), "=r"((r)[3]) : "r"(a))

__device__ __forceinline__ void mma_bf16(float* c, const uint32_t* a, const uint32_t* b) {
    asm volatile(
        "mma.sync.aligned.m16n8k16.row.col.f32.bf16.bf16.f32 "
        "{%0,%1,%2,%3}, {%4,%5,%6,%7}, {%8,%9}, {%0,%1,%2,%3};"
        : "+f"(c[0]), "+f"(c[1]), "+f"(c[2]), "+f"(c[3])
        : "r"(a[0]), "r"(a[1]), "r"(a[2]), "r"(a[3]), "r"(b[0]), "r"(b[1]));
}
__device__ __forceinline__ void cp_async16(uint32_t dst, const void* src) {
    asm volatile("cp.async.cg.shared.global [%0], [%1], 16;" :: "r"(dst), "l"(src));
}
#define CP_COMMIT() asm volatile("cp.async.commit_group;" ::: "memory")
#define CP_WAIT(n)  asm volatile("cp.async.wait_group %0;" :: "n"(n) : "memory")

__device__ __forceinline__ float sigm(float x) { return 1.f / (1.f + __expf(-x)); }
__device__ __forceinline__ float tanh_acc(float x) {
    float e = __expf(-2.f * fabsf(x));
    float t = (1.f - e) / (1.f + e);
    return copysignf(t, x);
}
__device__ __forceinline__ uint32_t pack_hl(float v) {
    __nv_bfloat16 h = __float2bfloat16(v);
    float hf = __bfloat162float(h);
    __nv_bfloat16 lo = __float2bfloat16(v - hf);
    return ((uint32_t)__bfloat16_as_ushort(h) << 16) | (uint32_t)__bfloat16_as_ushort(lo);
}
__device__ __forceinline__ int swz(int row, int kbyte) {
    return row * 64 + (kbyte ^ (((row >> 1) & 3) << 4));
}

// ---------------- small kernels ----------------
__global__ void zero_state_kernel(uint32_t* a, float* b, uint32_t* c, float* d, int n) {
    int i = blockIdx.x * blockDim.x + threadIdx.x;
    if (i < n) { a[i] = 0u; b[i] = 0.f; c[i] = 0u; d[i] = 0.f; }
}

__global__ void ln_kernel(const float* __restrict__ x,
                          const float* __restrict__ gamma,
                          const float* __restrict__ beta,
                          uint32_t* __restrict__ xn) {
    int idx = blockIdx.x * blockDim.x + threadIdx.x;
    if (idx >= BATCH * TSTEPS * NPIX) return;
    int p = idx % NPIX;
    int t = (idx / NPIX) % TSTEPS;
    int b = idx / (NPIX * TSTEPS);
    const float* base = x + ((long)(b * TSTEPS + t) * CIN) * NPIX + p;
    float v[CIN];
    float s = 0.f;
    #pragma unroll
    for (int c = 0; c < CIN; c++) { v[c] = base[c * NPIX]; s += v[c]; }
    float mu = s * (1.f / CIN);
    float q = 0.f;
    #pragma unroll
    for (int c = 0; c < CIN; c++) { float d = v[c] - mu; q += d * d; }
    float rs = rsqrtf(q * (1.f / CIN) + 1e-5f);
    uint32_t* ob = xn + ((long)(t * BATCH + b) * CIN) * NPIX + p;
    #pragma unroll
    for (int c = 0; c < CIN; c++) ob[c * NPIX] = pack_hl((v[c] - mu) * rs * gamma[c] + beta[c]);
}

// ---------------- merged prep: weight hi/lo conversion + tap tables ----------------
__device__ __forceinline__ void wconv(const float* W, __nv_bfloat16* hi, __nv_bfloat16* lo,
                                      int i, int Ktot, int Kpad, int perm) {
    int o = i / Kpad, k = i - o * Kpad;
    int orig = perm ? (((o >> 3) & 3) * 64 + ((o >> 7) & 1) * 32 + ((o >> 5) & 3) * 8 + (o & 7)) : o;
    float v = (k < Ktot) ? W[(long)orig * Ktot + k] : 0.f;
    __nv_bfloat16 h = __float2bfloat16(v);
    hi[i] = h;
    lo[i] = __float2bfloat16(v - __bfloat162float(h));
}
__device__ __forceinline__ int4 tap_make(int j, int Ktot, int C0) {
    if (j >= Ktot) return make_int4(0, 127, 127, 0);
    int cc = j / 9, r = j - cc * 9;
    int ky = r / 3 - 1, kx = r - (r / 3) * 3 - 1;
    int sel = cc >= C0;
    int c = sel ? cc - C0 : cc;
    return make_int4(c * NPIX + ky * SP + kx, ky, kx, sel);
}
__global__ void prep_kernel(const float* w0, const float* w1, const float* wc) {
    const int S0 = GATES * K0PAD, S1 = GATES * K1PAD, S2 = HID * KCPAD;
    int i = blockIdx.x * blockDim.x + threadIdx.x;
    if (i < S0) { wconv(w0, g_w0h, g_w0l, i, K0TOT, K0PAD, 1); return; }
    i -= S0;
    if (i < S1) { wconv(w1, g_w1h, g_w1l, i, K1TOT, K1PAD, 1); return; }
    i -= S1;
    if (i < S2) { wconv(wc, g_wch, g_wcl, i, KCTOT, KCPAD, 0); return; }
    i -= S2;
    if (i < K0PAD) { g_tap0[i] = tap_make(i, K0TOT, CIN); return; }
    i -= K0PAD;
    if (i < K1PAD) { g_tap1[i] = tap_make(i, K1TOT, HID); return; }
    i -= K1PAD;
    if (i < KCPAD) { g_tapc[i] = tap_make(i, KCTOT, HID); return; }
}

// ---------------- pipelined mma.sync implicit-GEMM conv (+fused epilogue) ----------------
template<int NWN, int EPI>
__global__ __launch_bounds__(NWN * 64, 2)
void convmma_kernel(const uint32_t* __restrict__ in0, int C0,
                    const uint32_t* __restrict__ in1, int C1,
                    const int4* __restrict__ tap,
                    const __nv_bfloat16* __restrict__ Whi,
                    const __nv_bfloat16* __restrict__ Wlo,
                    int Kpad,
                    const float* __restrict__ bias,
                    void* __restrict__ out_h_, float* __restrict__ out_c) {
    constexpr int NTH = NWN * 64;
    constexpr int NCH = NWN * 32;
    constexpr int APLANE = 128 * 64;
    constexpr int BPLANE = NCH * 64;
    constexpr int BUF = 2 * APLANE + 2 * BPLANE;
    constexpr int AE = 4096 / NTH;          // A elems per thread per stage
    constexpr int KST = (NTH == 256) ? 2 : 1;

    extern __shared__ char smem[];
    const uint32_t sb = smem_u32(smem);
    float* cs = (float*)(smem + 2 * BUF);
    uint32_t* hs = (uint32_t*)(smem + 2 * BUF + 128 * 36 * 4);

    const int tid = threadIdx.x;
    const int l = tid & 31;
    const int wid = tid >> 5;
    const int wm = wid & 1;
    const int wn = wid >> 1;
    const int img = blockIdx.y;
    const int pix0 = blockIdx.x * 128;
    const int nblk = blockIdx.z;
    const int nbase = nblk * NCH;

    const int arow = tid & 127;
    const int ap = pix0 + arow;
    const int apy = ap / SP;
    const int apx = ap - apy * SP;
    const bool apv = ap < NPIX;
    const int kbase = (NTH == 256) ? (tid >> 7) : 0;

    const uint32_t* in0i = in0 + (long)img * C0 * NPIX;
    const uint32_t* in1i = in1 + (long)img * C1 * NPIX;

    const int nstage = Kpad >> 5;

    uint32_t ar[AE];

    // issue A loads for stage s into ar (registers)
    auto ldgA = [&](int s) {
        const int k0 = s << 5;
        #pragma unroll
        for (int e = 0; e < AE; e++) {
            int kabs = k0 + kbase + e * KST;
            int4 t = __ldg(&tap[kabs]);
            const uint32_t* base = t.w ? in1i : in0i;
            bool valid = apv && (unsigned)(apy + t.y) < (unsigned)SP
                             && (unsigned)(apx + t.z) < (unsigned)SP;
            uint32_t v = 0;
            if (valid) v = __ldg(base + t.x + ap);
            ar[e] = v;
        }
    };
    // store ar into smem buffer for stage s
    auto stsA = [&](int s) {
        char* buf = smem + (s & 1) * BUF;
        #pragma unroll
        for (int e = 0; e < AE; e++) {
            int k = kbase + e * KST;
            int off = swz(arow, k * 2);
            *(uint16_t*)(buf + off) = (uint16_t)(ar[e] >> 16);
            *(uint16_t*)(buf + APLANE + off) = (uint16_t)(ar[e] & 0xffffu);
        }
    };
    // cp.async B tiles for stage s (+commit)
    auto cpB = [&](int s) {
        const uint32_t bb = sb + (s & 1) * BUF + 2 * APLANE;
        const int k0 = s << 5;
        const __nv_bfloat16* wh = Whi + k0;
        const __nv_bfloat16* wl = Wlo + k0;
        #pragma unroll
        for (int i = 0; i < NCH * 4 / NTH; i++) {
            int idx = tid + i * NTH;
            int n = idx >> 2, j = idx & 3;
            long wr = (long)(nbase + n) * Kpad + j * 8;
            int off = swz(n, j * 16);
            cp_async16(bb + off, wh + wr);
            cp_async16(bb + BPLANE + off, wl + wr);
        }
        CP_COMMIT();
    };

    float acc[4][4][4];
    #pragma unroll
    for (int a = 0; a < 4; a++)
        #pragma unroll
        for (int b = 0; b < 4; b++)
            #pragma unroll
            for (int c = 0; c < 4; c++) acc[a][b][c] = 0.f;

    // ---- prologue ----
    cpB(0);
    ldgA(0);
    stsA(0);
    cpB(1);
    ldgA(1);                 // stays in ar during stage 0 MMAs
    if (EPI == 0) {
        #pragma unroll
        for (int i = 0; i < 1024 / NTH; i++) {
            int idx4 = tid + i * NTH;
            int p = idx4 >> 3, jq = idx4 & 7;
            int pg = pix0 + p;
            float4 v = make_float4(0.f, 0.f, 0.f, 0.f);
            if (pg < NPIX)
                v = *(const float4*)(out_c + ((long)img * NPIX + pg) * 64 + nblk * 32 + jq * 4);
            *(float4*)(cs + p * 36 + jq * 4) = v;
        }
    }
    CP_WAIT(1);
    __syncthreads();

    for (int s = 0; s < nstage; s++) {
        // ---- MMAs on stage s ----
        const uint32_t cur = sb + (s & 1) * BUF;
        const uint32_t sAh = cur, sAl = cur + APLANE;
        const uint32_t sBh = cur + 2 * APLANE, sBl = sBh + BPLANE;

        #pragma unroll
        for (int h = 0; h < 2; h++) {
            uint32_t bh[2][4], bl[2][4];
            const int brow = wn * 32 + ((l >> 4) & 1) * 8 + (l & 7);
            const int bko = (h * 16 + ((l >> 3) & 1) * 8) * 2;
            #pragma unroll
            for (int nf2 = 0; nf2 < 2; nf2++) {
                LDSM4(bh[nf2], sBh + swz(brow + nf2 * 16, bko));
                LDSM4(bl[nf2], sBl + swz(brow + nf2 * 16, bko));
            }
            const int aro = wm * 64 + (l & 15);
            const int ako = (h * 16 + (l >> 4) * 8) * 2;
            #pragma unroll
            for (int mf = 0; mf < 4; mf++) {
                uint32_t ah[4], al[4];
                LDSM4(ah, sAh + swz(aro + mf * 16, ako));
                LDSM4(al, sAl + swz(aro + mf * 16, ako));
                #pragma unroll
                for (int nf = 0; nf < 4; nf++) {
                    const uint32_t* bhp = &bh[nf >> 1][(nf & 1) * 2];
                    const uint32_t* blp = &bl[nf >> 1][(nf & 1) * 2];
                    mma_bf16(acc[mf][nf], ah, bhp);
                    mma_bf16(acc[mf][nf], ah, blp);
                    mma_bf16(acc[mf][nf], al, bhp);
                }
            }
        }
        // ---- pipeline: store s+1 (already in regs), issue s+2 ----
        if (s + 1 < nstage) stsA(s + 1);
        if (s + 2 < nstage) {
            cpB(s + 2);
            ldgA(s + 2);
            CP_WAIT(1);      // B(s+1) complete; B(s+2) in flight
        } else {
            CP_WAIT(0);
        }
        __syncthreads();
    }

    if (EPI == 0) {
        #pragma unroll
        for (int mf = 0; mf < 4; mf++) {
            int pb = wm * 64 + mf * 16 + (l >> 2);
            #pragma unroll
            for (int c = 0; c < 4; c++) {
                int p = pb + ((c >> 1) & 1) * 8;
                int j = wn * 8 + (l & 3) * 2 + (c & 1);
                int u = nblk * 32 + j;
                float zi = acc[mf][0][c] + __ldg(bias + u);
                float zf = acc[mf][1][c] + __ldg(bias + 64 + u);
                float zo = acc[mf][2][c] + __ldg(bias + 128 + u);
                float zg = acc[mf][3][c] + __ldg(bias + 192 + u);
                if (pix0 + p < NPIX) {
                    float ig = sigm(zi), fg = sigm(zf), og = sigm(zo);
                    float gg = tanh_acc(zg);
                    float cn = fg * cs[p * 36 + j] + ig * gg;
                    cs[p * 36 + j] = cn;
                    hs[p * 33 + j] = pack_hl(og * tanh_acc(cn));
                }
            }
        }
        __syncthreads();
        uint32_t* out_h = (uint32_t*)out_h_;
        #pragma unroll
        for (int i = 0; i < 1024 / NTH; i++) {
            int idx4 = tid + i * NTH;
            int p = idx4 >> 3, jq = idx4 & 7;
            int pg = pix0 + p;
            if (pg < NPIX)
                *(float4*)(out_c + ((long)img * NPIX + pg) * 64 + nblk * 32 + jq * 4) =
                    *(const float4*)(cs + p * 36 + jq * 4);
        }
        #pragma unroll
        for (int uu = 0; uu < 32 * 32 / NTH; uu++) {
            int unit = (tid >> 5) + uu * (NTH / 32);
            #pragma unroll
            for (int i = 0; i < 4; i++) {
                int px = i * 32 + l;
                int pg = pix0 + px;
                if (pg < NPIX)
                    out_h[((long)img * HID + nblk * 32 + unit) * NPIX + pg] = hs[px * 33 + unit];
            }
        }
    } else {
        float* out_h = (float*)out_h_;
        #pragma unroll
        for (int mf = 0; mf < 4; mf++) {
            int pbase = pix0 + wm * 64 + mf * 16 + (l >> 2);
            #pragma unroll
            for (int c = 0; c < 4; c++) {
                int p = pbase + ((c >> 1) & 1) * 8;
                #pragma unroll
                for (int nf = 0; nf < 4; nf++) {
                    int n = wn * 32 + nf * 8 + (l & 3) * 2 + (c & 1);
                    float v = acc[mf][nf][c] + __ldg(bias + n);
                    if (p < NPIX)
                        out_h[((long)img * HID + n) * NPIX + p] = fmaxf(v, 0.f);
                }
            }
        }
    }
}

// ---------------- maxpool 2x2 stride 2 ----------------
__global__ void pool_kernel(const float* __restrict__ y, float* __restrict__ out) {
    int idx = blockIdx.x * blockDim.x + threadIdx.x;
    if (idx >= BATCH * HID * POOLD * POOLD) return;
    int j = idx % POOLD;
    int i = (idx / POOLD) % POOLD;
    int ch = (idx / (POOLD * POOLD)) % HID;
    int b = idx / (POOLD * POOLD * HID);
    const float* p = y + ((long)(b * HID + ch)) * NPIX + (2 * i) * SP + 2 * j;
    float m = fmaxf(fmaxf(p[0], p[1]), fmaxf(p[SP], p[SP + 1]));
    out[(long)b * FEAT + ch * (POOLD * POOLD) + i * POOLD + j] = m;
}

// ---------------- FC: one warp per output element ----------------
__global__ void fc_kernel(const float* __restrict__ in, const float* __restrict__ w,
                          const float* __restrict__ b, float* __restrict__ out,
                          int M, int N, int K, int relu) {
    int warp = (blockIdx.x * blockDim.x + threadIdx.x) >> 5;
    int lane = threadIdx.x & 31;
    if (warp >= M * N) return;
    int m = warp / N, n = warp - m * N;
    const float* ir = in + (long)m * K;
    const float* wr = w + (long)n * K;
    float s = 0.f;
    for (int k = lane; k < K; k += 32) s += ir[k] * wr[k];
    #pragma unroll
    for (int o = 16; o; o >>= 1) s += __shfl_xor_sync(0xFFFFFFFFu, s, o);
    if (lane == 0) {
        s += b[n];
        if (relu) s = fmaxf(s, 0.f);
        out[(long)m * N + n] = s;
    }
}

__global__ void lsm_kernel(const float* __restrict__ in, float* __restrict__ out) {
    int m = blockIdx.x * blockDim.x + threadIdx.x;
    if (m >= BATCH) return;
    float a = in[2 * m], b = in[2 * m + 1];
    float mx = fmaxf(a, b);
    float l = mx + logf(expf(a - mx) + expf(b - mx));
    out[2 * m] = a - l;
    out[2 * m + 1] = b - l;
}

// ---------------- launch ----------------
extern "C" void kernel_launch(void* const* d_in, const int* in_sizes, int n_in,
                              void* d_out, int out_size) {
    const float* x   = (const float*)d_in[0];
    const float* lg  = (const float*)d_in[1];
    const float* lb  = (const float*)d_in[2];
    const float* w0  = (const float*)d_in[3];
    const float* b0  = (const float*)d_in[4];
    const float* w1  = (const float*)d_in[5];
    const float* b1  = (const float*)d_in[6];
    const float* wc  = (const float*)d_in[7];
    const float* bc  = (const float*)d_in[8];
    const float* wf1 = (const float*)d_in[9];
    const float* bf1 = (const float*)d_in[10];
    const float* wf2 = (const float*)d_in[11];
    const float* bf2 = (const float*)d_in[12];
    const float* wf3 = (const float*)d_in[13];
    const float* bf3 = (const float*)d_in[14];
    float* out = (float*)d_out;

    uint32_t *xn, *h0a, *h0b, *h1a, *h1b;
    float *c0, *c1, *y, *pool, *f1, *f2, *f3;
    __nv_bfloat16 *w0h, *w0l, *w1h, *w1l, *wch, *wcl;
    int4 *tap0, *tap1, *tapc;
    cudaGetSymbolAddress((void**)&xn,  g_xn);
    cudaGetSymbolAddress((void**)&h0a, g_h0a);
    cudaGetSymbolAddress((void**)&h0b, g_h0b);
    cudaGetSymbolAddress((void**)&h1a, g_h1a);
    cudaGetSymbolAddress((void**)&h1b, g_h1b);
    cudaGetSymbolAddress((void**)&c0,  g_c0);
    cudaGetSymbolAddress((void**)&c1,  g_c1);
    cudaGetSymbolAddress((void**)&y,   g_y);
    cudaGetSymbolAddress((void**)&pool, g_pool);
    cudaGetSymbolAddress((void**)&f1, g_f1);
    cudaGetSymbolAddress((void**)&f2, g_f2);
    cudaGetSymbolAddress((void**)&f3, g_f3);
    cudaGetSymbolAddress((void**)&w0h, g_w0h);
    cudaGetSymbolAddress((void**)&w0l, g_w0l);
    cudaGetSymbolAddress((void**)&w1h, g_w1h);
    cudaGetSymbolAddress((void**)&w1l, g_w1l);
    cudaGetSymbolAddress((void**)&wch, g_wch);
    cudaGetSymbolAddress((void**)&wcl, g_wcl);
    cudaGetSymbolAddress((void**)&tap0, g_tap0);
    cudaGetSymbolAddress((void**)&tap1, g_tap1);
    cudaGetSymbolAddress((void**)&tapc, g_tapc);

    const int BUF0 = 2 * 128 * 64 + 2 * 128 * 64;
    const int SMEM0 = 2 * BUF0 + 128 * 36 * 4 + 128 * 33 * 4;   // 100864
    const int BUF1 = 2 * 128 * 64 + 2 * 64 * 64;
    const int SMEM1 = 2 * BUF1 + 128 * 36 * 4 + 128 * 33 * 4;   // margin (unused staging)
    cudaFuncSetAttribute(convmma_kernel<4, 0>, cudaFuncAttributeMaxDynamicSharedMemorySize, SMEM0);
    cudaFuncSetAttribute(convmma_kernel<2, 1>, cudaFuncAttributeMaxDynamicSharedMemorySize, SMEM1);

    const int nstate = BATCH * HID * NPIX;
    zero_state_kernel<<<(nstate + 255) / 256, 256>>>(h0a, c0, h1a, c1, nstate);

    const int nln = BATCH * TSTEPS * NPIX;
    ln_kernel<<<(nln + 255) / 256, 256>>>(x, lg, lb, xn);

    const int nprep = GATES * K0PAD + GATES * K1PAD + HID * KCPAD + K0PAD + K1PAD + KCPAD;
    prep_kernel<<<(nprep + 255) / 256, 256>>>(w0, w1, wc);

    uint32_t* h0buf[2] = {h0a, h0b};
    uint32_t* h1buf[2] = {h1a, h1b};
    dim3 grid0(5, BATCH, 2);
    for (int t = 0; t < TSTEPS; t++) {
        int r = t & 1;
        const uint32_t* xt = xn + (long)t * BATCH * CIN * NPIX;
        convmma_kernel<4, 0><<<grid0, 256, SMEM0>>>(
            xt, CIN, h0buf[r], HID, tap0, w0h, w0l, K0PAD, b0, h0buf[1 - r], c0);
        convmma_kernel<4, 0><<<grid0, 256, SMEM0>>>(
            h0buf[1 - r], HID, h1buf[r], HID, tap1, w1h, w1l, K1PAD, b1, h1buf[1 - r], c1);
    }
    const uint32_t* hfin = h1buf[0];   // t=19 (odd r) wrote h1buf[0]

    dim3 grid1(5, BATCH, 1);
    convmma_kernel<2, 1><<<grid1, 128, SMEM1>>>(
        hfin, HID, hfin, HID, tapc, wch, wcl, KCPAD, bc, y, (float*)0);

    const int npool = BATCH * HID * POOLD * POOLD;
    pool_kernel<<<(npool + 255) / 256, 256>>>(y, pool);
    {
        int warps = BATCH * FC1N;
        fc_kernel<<<(warps * 32 + 255) / 256, 256>>>(pool, wf1, bf1, f1, BATCH, FC1N, FEAT, 1);
    }
    {
        int warps = BATCH * FC2N;
        fc_kernel<<<(warps * 32 + 255) / 256, 256>>>(f1, wf2, bf2, f2, BATCH, FC2N, FC1N, 1);
    }
    {
        int warps = BATCH * 2;
        fc_kernel<<<(warps * 32 + 255) / 256, 256>>>(f2, wf3, bf3, f3, BATCH, 2, FC2N, 0);
    }
    lsm_kernel<<<1, BATCH>>>(f3, out);
}

// round 7
// speedup vs baseline: 3.1840x; 1.1021x over previous
#include <cuda_runtime.h>
#include <cuda_bf16.h>
#include <math.h>
#include <cstdint>

// ---------------- problem constants ----------------
#define BATCH 64
#define TSTEPS 20
#define CIN 25
#define HID 64
#define SP 25
#define NPIX 625
#define GATES 256
#define POOLD 12
#define FEAT 9216
#define FC1N 128
#define FC2N 64

#define K0TOT ((CIN + HID) * 9)   // 801
#define K0PAD 832                 // 26 stages of 32
#define K1TOT (2 * HID * 9)       // 1152
#define K1PAD 1152                // 36 stages
#define KCTOT (HID * 9)           // 576
#define KCPAD 576                 // 18 stages

// ---------------- scratch (device globals, no allocation) ----------------
// activations packed: u32 = (bf16 hi << 16) | bf16 lo
__device__ __align__(16) uint32_t g_xn[(long)TSTEPS * BATCH * CIN * NPIX];
__device__ __align__(16) uint32_t g_h0a[(long)BATCH * HID * NPIX];
__device__ __align__(16) uint32_t g_h0b[(long)BATCH * HID * NPIX];
__device__ __align__(16) uint32_t g_h1a[(long)BATCH * HID * NPIX];
__device__ __align__(16) uint32_t g_h1b[(long)BATCH * HID * NPIX];
__device__ __align__(16) float g_c0[(long)BATCH * NPIX * HID];
__device__ __align__(16) float g_c1[(long)BATCH * NPIX * HID];
__device__ __align__(16) float g_y [(long)BATCH * HID * NPIX];
__device__ __align__(16) float g_pool[(long)BATCH * FEAT];
__device__ float g_f1[BATCH * FC1N];
__device__ float g_f2[BATCH * FC2N];
__device__ float g_f3[BATCH * 2];
__device__ __align__(16) __nv_bfloat16 g_w0h[GATES * K0PAD];
__device__ __align__(16) __nv_bfloat16 g_w0l[GATES * K0PAD];
__device__ __align__(16) __nv_bfloat16 g_w1h[GATES * K1PAD];
__device__ __align__(16) __nv_bfloat16 g_w1l[GATES * K1PAD];
__device__ __align__(16) __nv_bfloat16 g_wch[HID * KCPAD];
__device__ __align__(16) __nv_bfloat16 g_wcl[HID * KCPAD];
__device__ __align__(16) int4 g_tap0[K0PAD];
__device__ __align__(16) int4 g_tap1[K1PAD];
__device__ __align__(16) int4 g_tapc[KCPAD];

// ---------------- helpers ----------------
__device__ __forceinline__ uint32_t smem_u32(const void* p) {
    uint32_t a;
    asm("{ .reg .u64 t; cvta.to.shared.u64 t, %1; cvt.u32.u64 %0, t; }" : "=r"(a) : "l"(p));
    return a;
}
#define LDSM4(r, a) \
    asm volatile("ldmatrix.sync.aligned.m8n8.x4.shared.b16 {%0,%1,%2,%3}, [%4];" \
        : "=r"((r)[0]), "=r"((r)[1]), "=r"((r)[2]), "=r"((r)[3]) : "r"(a))

__device__ __forceinline__ void mma_bf16(float* c, const uint32_t* a, const uint32_t* b) {
    asm volatile(
        "mma.sync.aligned.m16n8k16.row.col.f32.bf16.bf16.f32 "
        "{%0,%1,%2,%3}, {%4,%5,%6,%7}, {%8,%9}, {%0,%1,%2,%3};"
        : "+f"(c[0]), "+f"(c[1]), "+f"(c[2]), "+f"(c[3])
        : "r"(a[0]), "r"(a[1]), "r"(a[2]), "r"(a[3]), "r"(b[0]), "r"(b[1]));
}
__device__ __forceinline__ void cp_async16(uint32_t dst, const void* src) {
    asm volatile("cp.async.cg.shared.global [%0], [%1], 16;" :: "r"(dst), "l"(src));
}
#define CP_COMMIT() asm volatile("cp.async.commit_group;" ::: "memory")
#define CP_WAIT(n)  asm volatile("cp.async.wait_group %0;" :: "n"(n) : "memory")

__device__ __forceinline__ float sigm(float x) { return 1.f / (1.f + __expf(-x)); }
__device__ __forceinline__ float tanh_acc(float x) {
    float e = __expf(-2.f * fabsf(x));
    float t = (1.f - e) / (1.f + e);
    return copysignf(t, x);
}
__device__ __forceinline__ uint32_t pack_hl(float v) {
    __nv_bfloat16 h = __float2bfloat16(v);
    float hf = __bfloat162float(h);
    __nv_bfloat16 lo = __float2bfloat16(v - hf);
    return ((uint32_t)__bfloat16_as_ushort(h) << 16) | (uint32_t)__bfloat16_as_ushort(lo);
}
__device__ __forceinline__ int swz(int row, int kbyte) {
    return row * 64 + (kbyte ^ (((row >> 1) & 3) << 4));
}

// ---------------- small kernels ----------------
__global__ void zero_state_kernel(uint32_t* a, float* b, uint32_t* c, float* d, int n) {
    int i = blockIdx.x * blockDim.x + threadIdx.x;
    if (i < n) { a[i] = 0u; b[i] = 0.f; c[i] = 0u; d[i] = 0.f; }
}

__global__ void ln_kernel(const float* __restrict__ x,
                          const float* __restrict__ gamma,
                          const float* __restrict__ beta,
                          uint32_t* __restrict__ xn) {
    int idx = blockIdx.x * blockDim.x + threadIdx.x;
    if (idx >= BATCH * TSTEPS * NPIX) return;
    int p = idx % NPIX;
    int t = (idx / NPIX) % TSTEPS;
    int b = idx / (NPIX * TSTEPS);
    const float* base = x + ((long)(b * TSTEPS + t) * CIN) * NPIX + p;
    float v[CIN];
    float s = 0.f;
    #pragma unroll
    for (int c = 0; c < CIN; c++) { v[c] = base[c * NPIX]; s += v[c]; }
    float mu = s * (1.f / CIN);
    float q = 0.f;
    #pragma unroll
    for (int c = 0; c < CIN; c++) { float d = v[c] - mu; q += d * d; }
    float rs = rsqrtf(q * (1.f / CIN) + 1e-5f);
    uint32_t* ob = xn + ((long)(t * BATCH + b) * CIN) * NPIX + p;
    #pragma unroll
    for (int c = 0; c < CIN; c++) ob[c * NPIX] = pack_hl((v[c] - mu) * rs * gamma[c] + beta[c]);
}

// ---------------- merged prep: weight hi/lo conversion + tap tables ----------------
// perm (LSTM, 8 N-warps): GEMM row o -> orig channel gate*64 + unit,
//   gate=(o>>3)&3, unit=(o>>5)*8 + (o&7)
__device__ __forceinline__ void wconv(const float* W, __nv_bfloat16* hi, __nv_bfloat16* lo,
                                      int i, int Ktot, int Kpad, int perm) {
    int o = i / Kpad, k = i - o * Kpad;
    int orig = perm ? (((o >> 3) & 3) * 64 + (o >> 5) * 8 + (o & 7)) : o;
    float v = (k < Ktot) ? W[(long)orig * Ktot + k] : 0.f;
    __nv_bfloat16 h = __float2bfloat16(v);
    hi[i] = h;
    lo[i] = __float2bfloat16(v - __bfloat162float(h));
}
__device__ __forceinline__ int4 tap_make(int j, int Ktot, int C0) {
    if (j >= Ktot) return make_int4(0, 127, 127, 0);
    int cc = j / 9, r = j - cc * 9;
    int ky = r / 3 - 1, kx = r - (r / 3) * 3 - 1;
    int sel = cc >= C0;
    int c = sel ? cc - C0 : cc;
    return make_int4(c * NPIX + ky * SP + kx, ky, kx, sel);
}
__global__ void prep_kernel(const float* w0, const float* w1, const float* wc) {
    const int S0 = GATES * K0PAD, S1 = GATES * K1PAD, S2 = HID * KCPAD;
    int i = blockIdx.x * blockDim.x + threadIdx.x;
    if (i < S0) { wconv(w0, g_w0h, g_w0l, i, K0TOT, K0PAD, 1); return; }
    i -= S0;
    if (i < S1) { wconv(w1, g_w1h, g_w1l, i, K1TOT, K1PAD, 1); return; }
    i -= S1;
    if (i < S2) { wconv(wc, g_wch, g_wcl, i, KCTOT, KCPAD, 0); return; }
    i -= S2;
    if (i < K0PAD) { g_tap0[i] = tap_make(i, K0TOT, CIN); return; }
    i -= K0PAD;
    if (i < K1PAD) { g_tap1[i] = tap_make(i, K1TOT, HID); return; }
    i -= K1PAD;
    if (i < KCPAD) { g_tapc[i] = tap_make(i, KCTOT, HID); return; }
}

// ---------------- pipelined mma.sync implicit-GEMM conv (+fused epilogue) ----------------
// CTA: M=128 pixels x NCH=NWN*32 channels; warps (2 M) x (NWN N); warp tile 64x32.
// A packed u32 -> bf16 hi/lo smem planes; W bf16 hi/lo -> 3 MMAs per fragment.
// EPI=0 (NWN=8, 512 thr): all 256 gate channels, fused LSTM gates; h packed u32 out,
//        c fp32 pixel-major in/out via smem staging.
// EPI=1 (NWN=2, 128 thr): bias+relu, fp32 plane-major out.
template<int NWN, int EPI>
__global__ __launch_bounds__(NWN * 64, 1)
void convmma_kernel(const uint32_t* __restrict__ in0, int C0,
                    const uint32_t* __restrict__ in1, int C1,
                    const int4* __restrict__ tap,
                    const __nv_bfloat16* __restrict__ Whi,
                    const __nv_bfloat16* __restrict__ Wlo,
                    int Kpad,
                    const float* __restrict__ bias,
                    void* __restrict__ out_h_, float* __restrict__ out_c) {
    constexpr int NTH = NWN * 64;
    constexpr int NCH = NWN * 32;
    constexpr int APLANE = 128 * 64;        // one bf16 plane: 128 rows x 32 k x 2B
    constexpr int BPLANE = NCH * 64;
    constexpr int BUF = 2 * APLANE + 2 * BPLANE;
    constexpr int AE = 4096 / NTH;          // packed A elems per thread per stage
    constexpr int KST = NTH / 128;

    extern __shared__ char smem[];
    const uint32_t sb = smem_u32(smem);
    float* cs = (float*)(smem + 2 * BUF);                          // [128][68]
    uint32_t* hs = (uint32_t*)(smem + 2 * BUF + 128 * 68 * 4);     // [128][66]

    const int tid = threadIdx.x;
    const int l = tid & 31;
    const int wid = tid >> 5;
    const int wm = wid & 1;
    const int wn = wid >> 1;
    const int img = blockIdx.y;
    const int pix0 = blockIdx.x * 128;

    const int arow = tid & 127;
    const int ap = pix0 + arow;
    const int apy = ap / SP;
    const int apx = ap - apy * SP;
    const bool apv = ap < NPIX;
    const int kbase = tid >> 7;

    const uint32_t* in0i = in0 + (long)img * C0 * NPIX;
    const uint32_t* in1i = in1 + (long)img * C1 * NPIX;

    const int nstage = Kpad >> 5;

    uint32_t ar[AE];

    auto ldgA = [&](int s) {
        const int k0 = s << 5;
        #pragma unroll
        for (int e = 0; e < AE; e++) {
            int kabs = k0 + kbase + e * KST;
            int4 t = __ldg(&tap[kabs]);
            const uint32_t* base = t.w ? in1i : in0i;
            bool valid = apv && (unsigned)(apy + t.y) < (unsigned)SP
                             && (unsigned)(apx + t.z) < (unsigned)SP;
            uint32_t v = 0;
            if (valid) v = __ldg(base + t.x + ap);
            ar[e] = v;
        }
    };
    auto stsA = [&](int s) {
        char* buf = smem + (s & 1) * BUF;
        #pragma unroll
        for (int e = 0; e < AE; e++) {
            int k = kbase + e * KST;
            int off = swz(arow, k * 2);
            *(uint16_t*)(buf + off) = (uint16_t)(ar[e] >> 16);
            *(uint16_t*)(buf + APLANE + off) = (uint16_t)(ar[e] & 0xffffu);
        }
    };
    auto cpB = [&](int s) {
        const uint32_t bb = sb + (s & 1) * BUF + 2 * APLANE;
        const int k0 = s << 5;
        const __nv_bfloat16* wh = Whi + k0;
        const __nv_bfloat16* wl = Wlo + k0;
        #pragma unroll
        for (int i = 0; i < NCH * 4 / NTH; i++) {
            int idx = tid + i * NTH;
            int n = idx >> 2, j = idx & 3;
            long wr = (long)n * Kpad + j * 8;
            int off = swz(n, j * 16);
            cp_async16(bb + off, wh + wr);
            cp_async16(bb + BPLANE + off, wl + wr);
        }
        CP_COMMIT();
    };

    float acc[4][4][4];
    #pragma unroll
    for (int a = 0; a < 4; a++)
        #pragma unroll
        for (int b = 0; b < 4; b++)
            #pragma unroll
            for (int c = 0; c < 4; c++) acc[a][b][c] = 0.f;

    // ---- prologue ----
    cpB(0);
    ldgA(0);
    stsA(0);
    cpB(1);
    ldgA(1);
    if (EPI == 0) {
        #pragma unroll
        for (int i = 0; i < 2048 / NTH; i++) {
            int idx4 = tid + i * NTH;
            int p = idx4 >> 4, jq = idx4 & 15;
            int pg = pix0 + p;
            float4 v = make_float4(0.f, 0.f, 0.f, 0.f);
            if (pg < NPIX)
                v = *(const float4*)(out_c + ((long)img * NPIX + pg) * 64 + jq * 4);
            *(float4*)(cs + p * 68 + jq * 4) = v;
        }
    }
    CP_WAIT(1);
    __syncthreads();

    for (int s = 0; s < nstage; s++) {
        const uint32_t cur = sb + (s & 1) * BUF;
        const uint32_t sAh = cur, sAl = cur + APLANE;
        const uint32_t sBh = cur + 2 * APLANE, sBl = sBh + BPLANE;

        #pragma unroll
        for (int h = 0; h < 2; h++) {
            uint32_t bh[2][4], bl[2][4];
            const int brow = wn * 32 + ((l >> 4) & 1) * 8 + (l & 7);
            const int bko = (h * 16 + ((l >> 3) & 1) * 8) * 2;
            #pragma unroll
            for (int nf2 = 0; nf2 < 2; nf2++) {
                LDSM4(bh[nf2], sBh + swz(brow + nf2 * 16, bko));
                LDSM4(bl[nf2], sBl + swz(brow + nf2 * 16, bko));
            }
            const int aro = wm * 64 + (l & 15);
            const int ako = (h * 16 + (l >> 4) * 8) * 2;
            #pragma unroll
            for (int mf = 0; mf < 4; mf++) {
                uint32_t ah[4], al[4];
                LDSM4(ah, sAh + swz(aro + mf * 16, ako));
                LDSM4(al, sAl + swz(aro + mf * 16, ako));
                #pragma unroll
                for (int nf = 0; nf < 4; nf++) {
                    const uint32_t* bhp = &bh[nf >> 1][(nf & 1) * 2];
                    const uint32_t* blp = &bl[nf >> 1][(nf & 1) * 2];
                    mma_bf16(acc[mf][nf], ah, bhp);
                    mma_bf16(acc[mf][nf], ah, blp);
                    mma_bf16(acc[mf][nf], al, bhp);
                }
            }
        }
        if (s + 1 < nstage) stsA(s + 1);
        if (s + 2 < nstage) {
            cpB(s + 2);
            ldgA(s + 2);
            CP_WAIT(1);
        } else {
            CP_WAIT(0);
        }
        __syncthreads();
    }

    if (EPI == 0) {
        #pragma unroll
        for (int mf = 0; mf < 4; mf++) {
            #pragma unroll
            for (int c = 0; c < 4; c++) {
                int p = wm * 64 + mf * 16 + (l >> 2) + ((c >> 1) & 1) * 8;
                int j = wn * 8 + (l & 3) * 2 + (c & 1);
                float zi = acc[mf][0][c] + __ldg(bias + j);
                float zf = acc[mf][1][c] + __ldg(bias + 64 + j);
                float zo = acc[mf][2][c] + __ldg(bias + 128 + j);
                float zg = acc[mf][3][c] + __ldg(bias + 192 + j);
                if (pix0 + p < NPIX) {
                    float ig = sigm(zi), fg = sigm(zf), og = sigm(zo);
                    float gg = tanh_acc(zg);
                    float cn = fg * cs[p * 68 + j] + ig * gg;
                    cs[p * 68 + j] = cn;
                    hs[p * 66 + j] = pack_hl(og * tanh_acc(cn));
                }
            }
        }
        __syncthreads();
        uint32_t* out_h = (uint32_t*)out_h_;
        #pragma unroll
        for (int i = 0; i < 2048 / NTH; i++) {
            int idx4 = tid + i * NTH;
            int p = idx4 >> 4, jq = idx4 & 15;
            int pg = pix0 + p;
            if (pg < NPIX)
                *(float4*)(out_c + ((long)img * NPIX + pg) * 64 + jq * 4) =
                    *(const float4*)(cs + p * 68 + jq * 4);
        }
        #pragma unroll
        for (int uu = 0; uu < 64 * 32 / NTH; uu++) {   // 64 units
            int unit = wid + (NTH / 32) * uu;
            #pragma unroll
            for (int i = 0; i < 4; i++) {
                int px = i * 32 + l;
                int pg = pix0 + px;
                if (pg < NPIX)
                    out_h[((long)img * HID + unit) * NPIX + pg] = hs[px * 66 + unit];
            }
        }
    } else {
        float* out_h = (float*)out_h_;
        #pragma unroll
        for (int mf = 0; mf < 4; mf++) {
            #pragma unroll
            for (int c = 0; c < 4; c++) {
                int p = pix0 + wm * 64 + mf * 16 + (l >> 2) + ((c >> 1) & 1) * 8;
                #pragma unroll
                for (int nf = 0; nf < 4; nf++) {
                    int n = wn * 32 + nf * 8 + (l & 3) * 2 + (c & 1);
                    float v = acc[mf][nf][c] + __ldg(bias + n);
                    if (p < NPIX)
                        out_h[((long)img * HID + n) * NPIX + p] = fmaxf(v, 0.f);
                }
            }
        }
    }
}

// ---------------- maxpool 2x2 stride 2 ----------------
__global__ void pool_kernel(const float* __restrict__ y, float* __restrict__ out) {
    int idx = blockIdx.x * blockDim.x + threadIdx.x;
    if (idx >= BATCH * HID * POOLD * POOLD) return;
    int j = idx % POOLD;
    int i = (idx / POOLD) % POOLD;
    int ch = (idx / (POOLD * POOLD)) % HID;
    int b = idx / (POOLD * POOLD * HID);
    const float* p = y + ((long)(b * HID + ch)) * NPIX + (2 * i) * SP + 2 * j;
    float m = fmaxf(fmaxf(p[0], p[1]), fmaxf(p[SP], p[SP + 1]));
    out[(long)b * FEAT + ch * (POOLD * POOLD) + i * POOLD + j] = m;
}

// ---------------- FC: one warp per output element ----------------
__global__ void fc_kernel(const float* __restrict__ in, const float* __restrict__ w,
                          const float* __restrict__ b, float* __restrict__ out,
                          int M, int N, int K, int relu) {
    int warp = (blockIdx.x * blockDim.x + threadIdx.x) >> 5;
    int lane = threadIdx.x & 31;
    if (warp >= M * N) return;
    int m = warp / N, n = warp - m * N;
    const float* ir = in + (long)m * K;
    const float* wr = w + (long)n * K;
    float s = 0.f;
    for (int k = lane; k < K; k += 32) s += ir[k] * wr[k];
    #pragma unroll
    for (int o = 16; o; o >>= 1) s += __shfl_xor_sync(0xFFFFFFFFu, s, o);
    if (lane == 0) {
        s += b[n];
        if (relu) s = fmaxf(s, 0.f);
        out[(long)m * N + n] = s;
    }
}

__global__ void lsm_kernel(const float* __restrict__ in, float* __restrict__ out) {
    int m = blockIdx.x * blockDim.x + threadIdx.x;
    if (m >= BATCH) return;
    float a = in[2 * m], b = in[2 * m + 1];
    float mx = fmaxf(a, b);
    float l = mx + logf(expf(a - mx) + expf(b - mx));
    out[2 * m] = a - l;
    out[2 * m + 1] = b - l;
}

// ---------------- launch ----------------
extern "C" void kernel_launch(void* const* d_in, const int* in_sizes, int n_in,
                              void* d_out, int out_size) {
    const float* x   = (const float*)d_in[0];
    const float* lg  = (const float*)d_in[1];
    const float* lb  = (const float*)d_in[2];
    const float* w0  = (const float*)d_in[3];
    const float* b0  = (const float*)d_in[4];
    const float* w1  = (const float*)d_in[5];
    const float* b1  = (const float*)d_in[6];
    const float* wc  = (const float*)d_in[7];
    const float* bc  = (const float*)d_in[8];
    const float* wf1 = (const float*)d_in[9];
    const float* bf1 = (const float*)d_in[10];
    const float* wf2 = (const float*)d_in[11];
    const float* bf2 = (const float*)d_in[12];
    const float* wf3 = (const float*)d_in[13];
    const float* bf3 = (const float*)d_in[14];
    float* out = (float*)d_out;

    uint32_t *xn, *h0a, *h0b, *h1a, *h1b;
    float *c0, *c1, *y, *pool, *f1, *f2, *f3;
    __nv_bfloat16 *w0h, *w0l, *w1h, *w1l, *wch, *wcl;
    int4 *tap0, *tap1, *tapc;
    cudaGetSymbolAddress((void**)&xn,  g_xn);
    cudaGetSymbolAddress((void**)&h0a, g_h0a);
    cudaGetSymbolAddress((void**)&h0b, g_h0b);
    cudaGetSymbolAddress((void**)&h1a, g_h1a);
    cudaGetSymbolAddress((void**)&h1b, g_h1b);
    cudaGetSymbolAddress((void**)&c0,  g_c0);
    cudaGetSymbolAddress((void**)&c1,  g_c1);
    cudaGetSymbolAddress((void**)&y,   g_y);
    cudaGetSymbolAddress((void**)&pool, g_pool);
    cudaGetSymbolAddress((void**)&f1, g_f1);
    cudaGetSymbolAddress((void**)&f2, g_f2);
    cudaGetSymbolAddress((void**)&f3, g_f3);
    cudaGetSymbolAddress((void**)&w0h, g_w0h);
    cudaGetSymbolAddress((void**)&w0l, g_w0l);
    cudaGetSymbolAddress((void**)&w1h, g_w1h);
    cudaGetSymbolAddress((void**)&w1l, g_w1l);
    cudaGetSymbolAddress((void**)&wch, g_wch);
    cudaGetSymbolAddress((void**)&wcl, g_wcl);
    cudaGetSymbolAddress((void**)&tap0, g_tap0);
    cudaGetSymbolAddress((void**)&tap1, g_tap1);
    cudaGetSymbolAddress((void**)&tapc, g_tapc);

    // EPI0: BUF = 2*8192 + 2*16384 = 49152; x2 + staging
    const int BUF0 = 2 * 128 * 64 + 2 * 256 * 64;
    const int SMEM0 = 2 * BUF0 + 128 * 68 * 4 + 128 * 66 * 4;    // 166912
    const int BUF1 = 2 * 128 * 64 + 2 * 64 * 64;
    const int SMEM1 = 2 * BUF1;                                  // 49152
    cudaFuncSetAttribute(convmma_kernel<8, 0>, cudaFuncAttributeMaxDynamicSharedMemorySize, SMEM0);
    cudaFuncSetAttribute(convmma_kernel<2, 1>, cudaFuncAttributeMaxDynamicSharedMemorySize, SMEM1);

    const int nstate = BATCH * HID * NPIX;
    zero_state_kernel<<<(nstate + 255) / 256, 256>>>(h0a, c0, h1a, c1, nstate);

    const int nln = BATCH * TSTEPS * NPIX;
    ln_kernel<<<(nln + 255) / 256, 256>>>(x, lg, lb, xn);

    const int nprep = GATES * K0PAD + GATES * K1PAD + HID * KCPAD + K0PAD + K1PAD + KCPAD;
    prep_kernel<<<(nprep + 255) / 256, 256>>>(w0, w1, wc);

    uint32_t* h0buf[2] = {h0a, h0b};
    uint32_t* h1buf[2] = {h1a, h1b};
    dim3 grid0(5, BATCH);
    for (int t = 0; t < TSTEPS; t++) {
        int r = t & 1;
        const uint32_t* xt = xn + (long)t * BATCH * CIN * NPIX;
        convmma_kernel<8, 0><<<grid0, 512, SMEM0>>>(
            xt, CIN, h0buf[r], HID, tap0, w0h, w0l, K0PAD, b0, h0buf[1 - r], c0);
        convmma_kernel<8, 0><<<grid0, 512, SMEM0>>>(
            h0buf[1 - r], HID, h1buf[r], HID, tap1, w1h, w1l, K1PAD, b1, h1buf[1 - r], c1);
    }
    const uint32_t* hfin = h1buf[0];   // t=19 (r=1) wrote h1buf[0]

    dim3 grid1(5, BATCH);
    convmma_kernel<2, 1><<<grid1, 128, SMEM1>>>(
        hfin, HID, hfin, HID, tapc, wch, wcl, KCPAD, bc, y, (float*)0);

    const int npool = BATCH * HID * POOLD * POOLD;
    pool_kernel<<<(npool + 255) / 256, 256>>>(y, pool);
    {
        int warps = BATCH * FC1N;
        fc_kernel<<<(warps * 32 + 255) / 256, 256>>>(pool, wf1, bf1, f1, BATCH, FC1N, FEAT, 1);
    }
    {
        int warps = BATCH * FC2N;
        fc_kernel<<<(warps * 32 + 255) / 256, 256>>>(f1, wf2, bf2, f2, BATCH, FC2N, FC1N, 1);
    }
    {
        int warps = BATCH * 2;
        fc_kernel<<<(warps * 32 + 255) / 256, 256>>>(f2, wf3, bf3, f3, BATCH, 2, FC2N, 0);
    }
    lsm_kernel<<<1, BATCH>>>(f3, out);
}

// round 9
// speedup vs baseline: 3.2181x; 1.0107x over previous
#include <cuda_runtime.h>
#include <cuda_bf16.h>
#include <math.h>
#include <cstdint>

// ---------------- problem constants ----------------
#define BATCH 64
#define TSTEPS 20
#define CIN 25
#define HID 64
#define SP 25
#define NPIX 625
#define GATES 256
#define POOLD 12
#define FEAT 9216
#define FC1N 128
#define FC2N 64

#define K0TOT ((CIN + HID) * 9)   // 801
#define K0PAD 832                 // 26 stages of 32
#define K1TOT (2 * HID * 9)       // 1152
#define K1PAD 1152                // 36 stages
#define KCTOT (HID * 9)           // 576
#define KCPAD 576                 // 18 stages

// ---------------- scratch (device globals, no allocation) ----------------
// activations packed: u32 = (bf16 hi << 16) | bf16 lo
__device__ __align__(16) uint32_t g_xn[(long)TSTEPS * BATCH * CIN * NPIX];
__device__ __align__(16) uint32_t g_h0a[(long)BATCH * HID * NPIX];
__device__ __align__(16) uint32_t g_h0b[(long)BATCH * HID * NPIX];
__device__ __align__(16) uint32_t g_h1a[(long)BATCH * HID * NPIX];
__device__ __align__(16) uint32_t g_h1b[(long)BATCH * HID * NPIX];
__device__ __align__(16) float g_c0[(long)BATCH * NPIX * HID];
__device__ __align__(16) float g_c1[(long)BATCH * NPIX * HID];
__device__ __align__(16) float g_y [(long)BATCH * HID * NPIX];
__device__ __align__(16) float g_pool[(long)BATCH * FEAT];
__device__ float g_f1[BATCH * FC1N];
__device__ float g_f2[BATCH * FC2N];
__device__ float g_f3[BATCH * 2];
__device__ __align__(16) __nv_bfloat16 g_w0h[GATES * K0PAD];
__device__ __align__(16) __nv_bfloat16 g_w0l[GATES * K0PAD];
__device__ __align__(16) __nv_bfloat16 g_w1h[GATES * K1PAD];
__device__ __align__(16) __nv_bfloat16 g_w1l[GATES * K1PAD];
__device__ __align__(16) __nv_bfloat16 g_wch[HID * KCPAD];
__device__ __align__(16) __nv_bfloat16 g_wcl[HID * KCPAD];
__device__ __align__(16) int4 g_tap0[K0PAD];
__device__ __align__(16) int4 g_tap1[K1PAD];
__device__ __align__(16) int4 g_tapc[KCPAD];

// ---------------- helpers ----------------
__device__ __forceinline__ uint32_t smem_u32(const void* p) {
    uint32_t a;
    asm("{ .reg .u64 t; cvta.to.shared.u64 t, %1; cvt.u32.u64 %0, t; }" : "=r"(a) : "l"(p));
    return a;
}
#define LDSM4(r, a) \
    asm volatile("ldmatrix.sync.aligned.m8n8.x4.shared.b16 {%0,%1,%2,%3}, [%4];" \
        : "=r"((r)[0]), "=r"((r)[1]), "=r"((r)[2]), "=r"((r)[3]) : "r"(a))

__device__ __forceinline__ void mma_bf16(float* c, const uint32_t* a, const uint32_t* b) {
    asm volatile(
        "mma.sync.aligned.m16n8k16.row.col.f32.bf16.bf16.f32 "
        "{%0,%1,%2,%3}, {%4,%5,%6,%7}, {%8,%9}, {%0,%1,%2,%3};"
        : "+f"(c[0]), "+f"(c[1]), "+f"(c[2]), "+f"(c[3])
        : "r"(a[0]), "r"(a[1]), "r"(a[2]), "r"(a[3]), "r"(b[0]), "r"(b[1]));
}
__device__ __forceinline__ void cp_async16(uint32_t dst, const void* src) {
    asm volatile("cp.async.cg.shared.global [%0], [%1], 16;" :: "r"(dst), "l"(src));
}
#define CP_COMMIT() asm volatile("cp.async.commit_group;" ::: "memory")
#define CP_WAIT(n)  asm volatile("cp.async.wait_group %0;" :: "n"(n) : "memory")

__device__ __forceinline__ float sigm(float x) { return 1.f / (1.f + __expf(-x)); }
__device__ __forceinline__ float tanh_acc(float x) {
    float e = __expf(-2.f * fabsf(x));
    float t = (1.f - e) / (1.f + e);
    return copysignf(t, x);
}
__device__ __forceinline__ uint32_t pack_hl(float v) {
    __nv_bfloat16 h = __float2bfloat16(v);
    float hf = __bfloat162float(h);
    __nv_bfloat16 lo = __float2bfloat16(v - hf);
    return ((uint32_t)__bfloat16_as_ushort(h) << 16) | (uint32_t)__bfloat16_as_ushort(lo);
}
__device__ __forceinline__ int swz(int row, int kbyte) {
    return row * 64 + (kbyte ^ (((row >> 1) & 3) << 4));
}

// ---------------- small kernels ----------------
__global__ void zero_state_kernel(uint32_t* a, float* b, uint32_t* c, float* d, int n) {
    int i = blockIdx.x * blockDim.x + threadIdx.x;
    if (i < n) { a[i] = 0u; b[i] = 0.f; c[i] = 0u; d[i] = 0.f; }
}

__global__ void ln_kernel(const float* __restrict__ x,
                          const float* __restrict__ gamma,
                          const float* __restrict__ beta,
                          uint32_t* __restrict__ xn) {
    int idx = blockIdx.x * blockDim.x + threadIdx.x;
    if (idx >= BATCH * TSTEPS * NPIX) return;
    int p = idx % NPIX;
    int t = (idx / NPIX) % TSTEPS;
    int b = idx / (NPIX * TSTEPS);
    const float* base = x + ((long)(b * TSTEPS + t) * CIN) * NPIX + p;
    float v[CIN];
    float s = 0.f;
    #pragma unroll
    for (int c = 0; c < CIN; c++) { v[c] = base[c * NPIX]; s += v[c]; }
    float mu = s * (1.f / CIN);
    float q = 0.f;
    #pragma unroll
    for (int c = 0; c < CIN; c++) { float d = v[c] - mu; q += d * d; }
    float rs = rsqrtf(q * (1.f / CIN) + 1e-5f);
    uint32_t* ob = xn + ((long)(t * BATCH + b) * CIN) * NPIX + p;
    #pragma unroll
    for (int c = 0; c < CIN; c++) ob[c * NPIX] = pack_hl((v[c] - mu) * rs * gamma[c] + beta[c]);
}

// ---------------- merged prep: weight hi/lo conversion + tap tables ----------------
// perm (LSTM, 8 N-warps): GEMM row o -> orig channel gate*64 + unit,
//   gate=(o>>3)&3, unit=(o>>5)*8 + (o&7)
__device__ __forceinline__ void wconv(const float* W, __nv_bfloat16* hi, __nv_bfloat16* lo,
                                      int i, int Ktot, int Kpad, int perm) {
    int o = i / Kpad, k = i - o * Kpad;
    int orig = perm ? (((o >> 3) & 3) * 64 + (o >> 5) * 8 + (o & 7)) : o;
    float v = (k < Ktot) ? W[(long)orig * Ktot + k] : 0.f;
    __nv_bfloat16 h = __float2bfloat16(v);
    hi[i] = h;
    lo[i] = __float2bfloat16(v - __bfloat162float(h));
}
__device__ __forceinline__ int4 tap_make(int j, int Ktot, int C0) {
    if (j >= Ktot) return make_int4(0, 127, 127, 0);
    int cc = j / 9, r = j - cc * 9;
    int ky = r / 3 - 1, kx = r - (r / 3) * 3 - 1;
    int sel = cc >= C0;
    int c = sel ? cc - C0 : cc;
    return make_int4(c * NPIX + ky * SP + kx, ky, kx, sel);
}
__global__ void prep_kernel(const float* w0, const float* w1, const float* wc) {
    const int S0 = GATES * K0PAD, S1 = GATES * K1PAD, S2 = HID * KCPAD;
    int i = blockIdx.x * blockDim.x + threadIdx.x;
    if (i < S0) { wconv(w0, g_w0h, g_w0l, i, K0TOT, K0PAD, 1); return; }
    i -= S0;
    if (i < S1) { wconv(w1, g_w1h, g_w1l, i, K1TOT, K1PAD, 1); return; }
    i -= S1;
    if (i < S2) { wconv(wc, g_wch, g_wcl, i, KCTOT, KCPAD, 0); return; }
    i -= S2;
    if (i < K0PAD) { g_tap0[i] = tap_make(i, K0TOT, CIN); return; }
    i -= K0PAD;
    if (i < K1PAD) { g_tap1[i] = tap_make(i, K1TOT, HID); return; }
    i -= K1PAD;
    if (i < KCPAD) { g_tapc[i] = tap_make(i, KCTOT, HID); return; }
}

// ---------------- pipelined mma.sync implicit-GEMM conv (+fused epilogue) ----------------
// CTA: M=128 pixels x NCH=NWN*32 channels; warps (2 M) x (NWN N); warp tile 64x32.
// A packed u32 -> bf16 hi/lo smem planes; W bf16 hi/lo -> 3 MMAs per fragment,
// issued TERM-MAJOR over mf-pairs so same-acc HMMAs are >=8 MMAs apart.
// RACE-FREE schedule: cp.async B prefetch distance 1, issued at loop top into
// the buffer all warps released at the previous barrier; CP_WAIT(0) before barrier.
// EPI=0 (NWN=8, 512 thr): all 256 gate channels, fused LSTM gates.
// EPI=1 (NWN=2, 128 thr): bias+relu, fp32 plane-major out.
template<int NWN, int EPI>
__global__ __launch_bounds__(NWN * 64, 1)
void convmma_kernel(const uint32_t* __restrict__ in0, int C0,
                    const uint32_t* __restrict__ in1, int C1,
                    const int4* __restrict__ tap,
                    const __nv_bfloat16* __restrict__ Whi,
                    const __nv_bfloat16* __restrict__ Wlo,
                    int Kpad,
                    const float* __restrict__ bias,
                    void* __restrict__ out_h_, float* __restrict__ out_c) {
    constexpr int NTH = NWN * 64;
    constexpr int NCH = NWN * 32;
    constexpr int APLANE = 128 * 64;        // one bf16 plane: 128 rows x 32 k x 2B
    constexpr int BPLANE = NCH * 64;
    constexpr int BUF = 2 * APLANE + 2 * BPLANE;
    constexpr int AE = 4096 / NTH;          // packed A elems per thread per stage
    constexpr int KST = NTH / 128;

    extern __shared__ char smem[];
    const uint32_t sb = smem_u32(smem);
    float* cs = (float*)(smem + 2 * BUF);                          // [128][68]
    uint32_t* hs = (uint32_t*)(smem + 2 * BUF + 128 * 68 * 4);     // [128][66]

    const int tid = threadIdx.x;
    const int l = tid & 31;
    const int wid = tid >> 5;
    const int wm = wid & 1;
    const int wn = wid >> 1;
    const int img = blockIdx.y;
    const int pix0 = blockIdx.x * 128;

    const int arow = tid & 127;
    const int ap = pix0 + arow;
    const int apy = ap / SP;
    const int apx = ap - apy * SP;
    const bool apv = ap < NPIX;
    const int kbase = tid >> 7;

    const uint32_t* in0i = in0 + (long)img * C0 * NPIX;
    const uint32_t* in1i = in1 + (long)img * C1 * NPIX;

    const int nstage = Kpad >> 5;

    uint32_t ar[AE];

    auto ldgA = [&](int s) {
        const int k0 = s << 5;
        #pragma unroll
        for (int e = 0; e < AE; e++) {
            int kabs = k0 + kbase + e * KST;
            int4 t = __ldg(&tap[kabs]);
            const uint32_t* base = t.w ? in1i : in0i;
            bool valid = apv && (unsigned)(apy + t.y) < (unsigned)SP
                             && (unsigned)(apx + t.z) < (unsigned)SP;
            uint32_t v = 0;
            if (valid) v = __ldg(base + t.x + ap);
            ar[e] = v;
        }
    };
    auto stsA = [&](int s) {
        char* buf = smem + (s & 1) * BUF;
        #pragma unroll
        for (int e = 0; e < AE; e++) {
            int k = kbase + e * KST;
            int off = swz(arow, k * 2);
            *(uint16_t*)(buf + off) = (uint16_t)(ar[e] >> 16);
            *(uint16_t*)(buf + APLANE + off) = (uint16_t)(ar[e] & 0xffffu);
        }
    };
    auto cpB = [&](int s) {
        const uint32_t bb = sb + (s & 1) * BUF + 2 * APLANE;
        const int k0 = s << 5;
        const __nv_bfloat16* wh = Whi + k0;
        const __nv_bfloat16* wl = Wlo + k0;
        #pragma unroll
        for (int i = 0; i < NCH * 4 / NTH; i++) {
            int idx = tid + i * NTH;
            int n = idx >> 2, j = idx & 3;
            long wr = (long)n * Kpad + j * 8;
            int off = swz(n, j * 16);
            cp_async16(bb + off, wh + wr);
            cp_async16(bb + BPLANE + off, wl + wr);
        }
        CP_COMMIT();
    };

    float acc[4][4][4];
    #pragma unroll
    for (int a = 0; a < 4; a++)
        #pragma unroll
        for (int b = 0; b < 4; b++)
            #pragma unroll
            for (int c = 0; c < 4; c++) acc[a][b][c] = 0.f;

    // ---- prologue: stage 0 fully resident before loop ----
    cpB(0);
    ldgA(0);
    stsA(0);
    ldgA(1);                 // regs for stsA(1) in iter 0
    if (EPI == 0) {
        #pragma unroll
        for (int i = 0; i < 2048 / NTH; i++) {
            int idx4 = tid + i * NTH;
            int p = idx4 >> 4, jq = idx4 & 15;
            int pg = pix0 + p;
            float4 v = make_float4(0.f, 0.f, 0.f, 0.f);
            if (pg < NPIX)
                v = *(const float4*)(out_c + ((long)img * NPIX + pg) * 64 + jq * 4);
            *(float4*)(cs + p * 68 + jq * 4) = v;
        }
    }
    CP_WAIT(0);
    __syncthreads();

    for (int s = 0; s < nstage; s++) {
        // B prefetch for s+1 into buffer (s+1)&1 — released by all warps at the
        // previous barrier (its stage s-1 data was last read in iteration s-1).
        if (s + 1 < nstage) cpB(s + 1);

        const uint32_t cur = sb + (s & 1) * BUF;
        const uint32_t sAh = cur, sAl = cur + APLANE;
        const uint32_t sBh = cur + 2 * APLANE, sBl = sBh + BPLANE;

        #pragma unroll
        for (int h = 0; h < 2; h++) {
            uint32_t bh[2][4], bl[2][4];
            const int brow = wn * 32 + ((l >> 4) & 1) * 8 + (l & 7);
            const int bko = (h * 16 + ((l >> 3) & 1) * 8) * 2;
            #pragma unroll
            for (int nf2 = 0; nf2 < 2; nf2++) {
                LDSM4(bh[nf2], sBh + swz(brow + nf2 * 16, bko));
                LDSM4(bl[nf2], sBl + swz(brow + nf2 * 16, bko));
            }
            const int aro = wm * 64 + (l & 15);
            const int ako = (h * 16 + (l >> 4) * 8) * 2;
            // term-major over mf-pairs: dependent same-acc MMAs 8 apart
            #pragma unroll
            for (int mfp = 0; mfp < 2; mfp++) {
                uint32_t ah[2][4], al[2][4];
                #pragma unroll
                for (int mi = 0; mi < 2; mi++) {
                    int mf = mfp * 2 + mi;
                    LDSM4(ah[mi], sAh + swz(aro + mf * 16, ako));
                    LDSM4(al[mi], sAl + swz(aro + mf * 16, ako));
                }
                #pragma unroll
                for (int mi = 0; mi < 2; mi++)
                    #pragma unroll
                    for (int nf = 0; nf < 4; nf++)
                        mma_bf16(acc[mfp * 2 + mi][nf], ah[mi], &bh[nf >> 1][(nf & 1) * 2]);
                #pragma unroll
                for (int mi = 0; mi < 2; mi++)
                    #pragma unroll
                    for (int nf = 0; nf < 4; nf++)
                        mma_bf16(acc[mfp * 2 + mi][nf], ah[mi], &bl[nf >> 1][(nf & 1) * 2]);
                #pragma unroll
                for (int mi = 0; mi < 2; mi++)
                    #pragma unroll
                    for (int nf = 0; nf < 4; nf++)
                        mma_bf16(acc[mfp * 2 + mi][nf], al[mi], &bh[nf >> 1][(nf & 1) * 2]);
            }
        }
        // A: store stage s+1 (regs loaded last iter), then load stage s+2 regs
        if (s + 1 < nstage) stsA(s + 1);
        if (s + 2 < nstage) ldgA(s + 2);
        CP_WAIT(0);          // B(s+1) landed; whole MMA block covered the latency
        __syncthreads();
    }

    if (EPI == 0) {
        #pragma unroll
        for (int mf = 0; mf < 4; mf++) {
            #pragma unroll
            for (int c = 0; c < 4; c++) {
                int p = wm * 64 + mf * 16 + (l >> 2) + ((c >> 1) & 1) * 8;
                int j = wn * 8 + (l & 3) * 2 + (c & 1);
                float zi = acc[mf][0][c] + __ldg(bias + j);
                float zf = acc[mf][1][c] + __ldg(bias + 64 + j);
                float zo = acc[mf][2][c] + __ldg(bias + 128 + j);
                float zg = acc[mf][3][c] + __ldg(bias + 192 + j);
                if (pix0 + p < NPIX) {
                    float ig = sigm(zi), fg = sigm(zf), og = sigm(zo);
                    float gg = tanh_acc(zg);
                    float cn = fg * cs[p * 68 + j] + ig * gg;
                    cs[p * 68 + j] = cn;
                    hs[p * 66 + j] = pack_hl(og * tanh_acc(cn));
                }
            }
        }
        __syncthreads();
        uint32_t* out_h = (uint32_t*)out_h_;
        #pragma unroll
        for (int i = 0; i < 2048 / NTH; i++) {
            int idx4 = tid + i * NTH;
            int p = idx4 >> 4, jq = idx4 & 15;
            int pg = pix0 + p;
            if (pg < NPIX)
                *(float4*)(out_c + ((long)img * NPIX + pg) * 64 + jq * 4) =
                    *(const float4*)(cs + p * 68 + jq * 4);
        }
        #pragma unroll
        for (int uu = 0; uu < 64 * 32 / NTH; uu++) {   // 64 units
            int unit = wid + (NTH / 32) * uu;
            #pragma unroll
            for (int i = 0; i < 4; i++) {
                int px = i * 32 + l;
                int pg = pix0 + px;
                if (pg < NPIX)
                    out_h[((long)img * HID + unit) * NPIX + pg] = hs[px * 66 + unit];
            }
        }
    } else {
        float* out_h = (float*)out_h_;
        #pragma unroll
        for (int mf = 0; mf < 4; mf++) {
            #pragma unroll
            for (int c = 0; c < 4; c++) {
                int p = pix0 + wm * 64 + mf * 16 + (l >> 2) + ((c >> 1) & 1) * 8;
                #pragma unroll
                for (int nf = 0; nf < 4; nf++) {
                    int n = wn * 32 + nf * 8 + (l & 3) * 2 + (c & 1);
                    float v = acc[mf][nf][c] + __ldg(bias + n);
                    if (p < NPIX)
                        out_h[((long)img * HID + n) * NPIX + p] = fmaxf(v, 0.f);
                }
            }
        }
    }
}

// ---------------- maxpool 2x2 stride 2 ----------------
__global__ void pool_kernel(const float* __restrict__ y, float* __restrict__ out) {
    int idx = blockIdx.x * blockDim.x + threadIdx.x;
    if (idx >= BATCH * HID * POOLD * POOLD) return;
    int j = idx % POOLD;
    int i = (idx / POOLD) % POOLD;
    int ch = (idx / (POOLD * POOLD)) % HID;
    int b = idx / (POOLD * POOLD * HID);
    const float* p = y + ((long)(b * HID + ch)) * NPIX + (2 * i) * SP + 2 * j;
    float m = fmaxf(fmaxf(p[0], p[1]), fmaxf(p[SP], p[SP + 1]));
    out[(long)b * FEAT + ch * (POOLD * POOLD) + i * POOLD + j] = m;
}

// ---------------- FC: one warp per output element ----------------
__global__ void fc_kernel(const float* __restrict__ in, const float* __restrict__ w,
                          const float* __restrict__ b, float* __restrict__ out,
                          int M, int N, int K, int relu) {
    int warp = (blockIdx.x * blockDim.x + threadIdx.x) >> 5;
    int lane = threadIdx.x & 31;
    if (warp >= M * N) return;
    int m = warp / N, n = warp - m * N;
    const float* ir = in + (long)m * K;
    const float* wr = w + (long)n * K;
    float s = 0.f;
    for (int k = lane; k < K; k += 32) s += ir[k] * wr[k];
    #pragma unroll
    for (int o = 16; o; o >>= 1) s += __shfl_xor_sync(0xFFFFFFFFu, s, o);
    if (lane == 0) {
        s += b[n];
        if (relu) s = fmaxf(s, 0.f);
        out[(long)m * N + n] = s;
    }
}

__global__ void lsm_kernel(const float* __restrict__ in, float* __restrict__ out) {
    int m = blockIdx.x * blockDim.x + threadIdx.x;
    if (m >= BATCH) return;
    float a = in[2 * m], b = in[2 * m + 1];
    float mx = fmaxf(a, b);
    float l = mx + logf(expf(a - mx) + expf(b - mx));
    out[2 * m] = a - l;
    out[2 * m + 1] = b - l;
}

// ---------------- launch ----------------
extern "C" void kernel_launch(void* const* d_in, const int* in_sizes, int n_in,
                              void* d_out, int out_size) {
    const float* x   = (const float*)d_in[0];
    const float* lg  = (const float*)d_in[1];
    const float* lb  = (const float*)d_in[2];
    const float* w0  = (const float*)d_in[3];
    const float* b0  = (const float*)d_in[4];
    const float* w1  = (const float*)d_in[5];
    const float* b1  = (const float*)d_in[6];
    const float* wc  = (const float*)d_in[7];
    const float* bc  = (const float*)d_in[8];
    const float* wf1 = (const float*)d_in[9];
    const float* bf1 = (const float*)d_in[10];
    const float* wf2 = (const float*)d_in[11];
    const float* bf2 = (const float*)d_in[12];
    const float* wf3 = (const float*)d_in[13];
    const float* bf3 = (const float*)d_in[14];
    float* out = (float*)d_out;

    uint32_t *xn, *h0a, *h0b, *h1a, *h1b;
    float *c0, *c1, *y, *pool, *f1, *f2, *f3;
    __nv_bfloat16 *w0h, *w0l, *w1h, *w1l, *wch, *wcl;
    int4 *tap0, *tap1, *tapc;
    cudaGetSymbolAddress((void**)&xn,  g_xn);
    cudaGetSymbolAddress((void**)&h0a, g_h0a);
    cudaGetSymbolAddress((void**)&h0b, g_h0b);
    cudaGetSymbolAddress((void**)&h1a, g_h1a);
    cudaGetSymbolAddress((void**)&h1b, g_h1b);
    cudaGetSymbolAddress((void**)&c0,  g_c0);
    cudaGetSymbolAddress((void**)&c1,  g_c1);
    cudaGetSymbolAddress((void**)&y,   g_y);
    cudaGetSymbolAddress((void**)&pool, g_pool);
    cudaGetSymbolAddress((void**)&f1, g_f1);
    cudaGetSymbolAddress((void**)&f2, g_f2);
    cudaGetSymbolAddress((void**)&f3, g_f3);
    cudaGetSymbolAddress((void**)&w0h, g_w0h);
    cudaGetSymbolAddress((void**)&w0l, g_w0l);
    cudaGetSymbolAddress((void**)&w1h, g_w1h);
    cudaGetSymbolAddress((void**)&w1l, g_w1l);
    cudaGetSymbolAddress((void**)&wch, g_wch);
    cudaGetSymbolAddress((void**)&wcl, g_wcl);
    cudaGetSymbolAddress((void**)&tap0, g_tap0);
    cudaGetSymbolAddress((void**)&tap1, g_tap1);
    cudaGetSymbolAddress((void**)&tapc, g_tapc);

    const int BUF0 = 2 * 128 * 64 + 2 * 256 * 64;
    const int SMEM0 = 2 * BUF0 + 128 * 68 * 4 + 128 * 66 * 4;    // 166912
    const int BUF1 = 2 * 128 * 64 + 2 * 64 * 64;
    const int SMEM1 = 2 * BUF1;                                  // 49152
    cudaFuncSetAttribute(convmma_kernel<8, 0>, cudaFuncAttributeMaxDynamicSharedMemorySize, SMEM0);
    cudaFuncSetAttribute(convmma_kernel<2, 1>, cudaFuncAttributeMaxDynamicSharedMemorySize, SMEM1);

    const int nstate = BATCH * HID * NPIX;
    zero_state_kernel<<<(nstate + 255) / 256, 256>>>(h0a, c0, h1a, c1, nstate);

    const int nln = BATCH * TSTEPS * NPIX;
    ln_kernel<<<(nln + 255) / 256, 256>>>(x, lg, lb, xn);

    const int nprep = GATES * K0PAD + GATES * K1PAD + HID * KCPAD + K0PAD + K1PAD + KCPAD;
    prep_kernel<<<(nprep + 255) / 256, 256>>>(w0, w1, wc);

    uint32_t* h0buf[2] = {h0a, h0b};
    uint32_t* h1buf[2] = {h1a, h1b};
    dim3 grid0(5, BATCH);
    for (int t = 0; t < TSTEPS; t++) {
        int r = t & 1;
        const uint32_t* xt = xn + (long)t * BATCH * CIN * NPIX;
        convmma_kernel<8, 0><<<grid0, 512, SMEM0>>>(
            xt, CIN, h0buf[r], HID, tap0, w0h, w0l, K0PAD, b0, h0buf[1 - r], c0);
        convmma_kernel<8, 0><<<grid0, 512, SMEM0>>>(
            h0buf[1 - r], HID, h1buf[r], HID, tap1, w1h, w1l, K1PAD, b1, h1buf[1 - r], c1);
    }
    const uint32_t* hfin = h1buf[0];   // t=19 (r=1) wrote h1buf[0]

    dim3 grid1(5, BATCH);
    convmma_kernel<2, 1><<<grid1, 128, SMEM1>>>(
        hfin, HID, hfin, HID, tapc, wch, wcl, KCPAD, bc, y, (float*)0);

    const int npool = BATCH * HID * POOLD * POOLD;
    pool_kernel<<<(npool + 255) / 256, 256>>>(y, pool);
    {
        int warps = BATCH * FC1N;
        fc_kernel<<<(warps * 32 + 255) / 256, 256>>>(pool, wf1, bf1, f1, BATCH, FC1N, FEAT, 1);
    }
    {
        int warps = BATCH * FC2N;
        fc_kernel<<<(warps * 32 + 255) / 256, 256>>>(f1, wf2, bf2, f2, BATCH, FC2N, FC1N, 1);
    }
    {
        int warps = BATCH * 2;
        fc_kernel<<<(warps * 32 + 255) / 256, 256>>>(f2, wf3, bf3, f3, BATCH, 2, FC2N, 0);
    }
    lsm_kernel<<<1, BATCH>>>(f3, out);
}

// round 10
// speedup vs baseline: 3.5180x; 1.0932x over previous
#include <cuda_runtime.h>
#include <cuda_bf16.h>
#include <math.h>
#include <cstdint>

// ---------------- problem constants ----------------
#define BATCH 64
#define TSTEPS 20
#define CIN 25
#define HID 64
#define SP 25
#define NPIX 625
#define GATES 256
#define POOLD 12
#define FEAT 9216
#define FC1N 128
#define FC2N 64

#define PW 27                 // padded plane width (25 + border)
#define PPLANE 729            // 27*27

#define K0TOT ((CIN + HID) * 9)   // 801
#define K0PAD 832                 // 26 stages of 32
#define K1TOT (2 * HID * 9)       // 1152
#define K1PAD 1152                // 36 stages
#define KCTOT (HID * 9)           // 576
#define KCPAD 576                 // 18 stages
#define TAPSZ 9216                // 1152 * sizeof(int2)

// ---------------- scratch (device globals, no allocation) ----------------
// activations packed u32 = (bf16 hi << 16) | bf16 lo, in 27x27 zero-bordered
// planes; each image has one extra always-zero plane at channel index C.
__device__ __align__(16) uint32_t g_xn[(long)TSTEPS * BATCH * (CIN + 1) * PPLANE];
__device__ __align__(16) uint32_t g_h0a[(long)BATCH * (HID + 1) * PPLANE];
__device__ __align__(16) uint32_t g_h0b[(long)BATCH * (HID + 1) * PPLANE];
__device__ __align__(16) uint32_t g_h1a[(long)BATCH * (HID + 1) * PPLANE];
__device__ __align__(16) uint32_t g_h1b[(long)BATCH * (HID + 1) * PPLANE];
__device__ __align__(16) float g_c0[(long)BATCH * NPIX * HID];
__device__ __align__(16) float g_c1[(long)BATCH * NPIX * HID];
__device__ __align__(16) float g_y [(long)BATCH * HID * NPIX];
__device__ __align__(16) float g_pool[(long)BATCH * FEAT];
__device__ float g_f1[BATCH * FC1N];
__device__ float g_f2[BATCH * FC2N];
__device__ float g_f3[BATCH * 2];
__device__ __align__(16) __nv_bfloat16 g_w0h[GATES * K0PAD];
__device__ __align__(16) __nv_bfloat16 g_w0l[GATES * K0PAD];
__device__ __align__(16) __nv_bfloat16 g_w1h[GATES * K1PAD];
__device__ __align__(16) __nv_bfloat16 g_w1l[GATES * K1PAD];
__device__ __align__(16) __nv_bfloat16 g_wch[HID * KCPAD];
__device__ __align__(16) __nv_bfloat16 g_wcl[HID * KCPAD];
__device__ __align__(16) int2 g_tap0[K0PAD];
__device__ __align__(16) int2 g_tap1[K1PAD];
__device__ __align__(16) int2 g_tapc[KCPAD];

// ---------------- helpers ----------------
__device__ __forceinline__ uint32_t smem_u32(const void* p) {
    uint32_t a;
    asm("{ .reg .u64 t; cvta.to.shared.u64 t, %1; cvt.u32.u64 %0, t; }" : "=r"(a) : "l"(p));
    return a;
}
#define LDSM4(r, a) \
    asm volatile("ldmatrix.sync.aligned.m8n8.x4.shared.b16 {%0,%1,%2,%3}, [%4];" \
        : "=r"((r)[0]), "=r"((r)[1]), "=r"((r)[2]), "=r"((r)[3]) : "r"(a))

__device__ __forceinline__ void mma_bf16(float* c, const uint32_t* a, const uint32_t* b) {
    asm volatile(
        "mma.sync.aligned.m16n8k16.row.col.f32.bf16.bf16.f32 "
        "{%0,%1,%2,%3}, {%4,%5,%6,%7}, {%8,%9}, {%0,%1,%2,%3};"
        : "+f"(c[0]), "+f"(c[1]), "+f"(c[2]), "+f"(c[3])
        : "r"(a[0]), "r"(a[1]), "r"(a[2]), "r"(a[3]), "r"(b[0]), "r"(b[1]));
}
__device__ __forceinline__ void cp_async16(uint32_t dst, const void* src) {
    asm volatile("cp.async.cg.shared.global [%0], [%1], 16;" :: "r"(dst), "l"(src));
}
#define CP_COMMIT() asm volatile("cp.async.commit_group;" ::: "memory")
#define CP_WAIT(n)  asm volatile("cp.async.wait_group %0;" :: "n"(n) : "memory")

__device__ __forceinline__ float sigm(float x) { return 1.f / (1.f + __expf(-x)); }
__device__ __forceinline__ float tanh_acc(float x) {
    float e = __expf(-2.f * fabsf(x));
    float t = (1.f - e) / (1.f + e);
    return copysignf(t, x);
}
__device__ __forceinline__ uint32_t pack_hl(float v) {
    __nv_bfloat16 h = __float2bfloat16(v);
    float hf = __bfloat162float(h);
    __nv_bfloat16 lo = __float2bfloat16(v - hf);
    return ((uint32_t)__bfloat16_as_ushort(h) << 16) | (uint32_t)__bfloat16_as_ushort(lo);
}
__device__ __forceinline__ int swz(int row, int kbyte) {
    return row * 64 + (kbyte ^ (((row >> 1) & 3) << 4));
}

// ---------------- zero all recurrent/padded state ----------------
#define NXZ ((long)TSTEPS * BATCH * (CIN + 1) * PPLANE)   // 24,261,120
#define NHZ ((long)BATCH * (HID + 1) * PPLANE)            // 3,032,640
#define NCZ ((long)BATCH * NPIX * HID)                    // 2,560,000
__global__ void zero_all_kernel(uint32_t* xn, uint32_t* h0a, uint32_t* h0b,
                                uint32_t* h1a, uint32_t* h1b, float* c0, float* c1) {
    long i = (long)blockIdx.x * blockDim.x + threadIdx.x;
    if (i < NXZ) xn[i] = 0u;
    if (i < NHZ) { h0a[i] = 0u; h0b[i] = 0u; h1a[i] = 0u; h1b[i] = 0u; }
    if (i < NCZ) { c0[i] = 0.f; c1[i] = 0.f; }
}

// ---------------- LayerNorm -> padded planes ----------------
__global__ void ln_kernel(const float* __restrict__ x,
                          const float* __restrict__ gamma,
                          const float* __restrict__ beta,
                          uint32_t* __restrict__ xn) {
    int idx = blockIdx.x * blockDim.x + threadIdx.x;
    if (idx >= BATCH * TSTEPS * NPIX) return;
    int p = idx % NPIX;
    int t = (idx / NPIX) % TSTEPS;
    int b = idx / (NPIX * TSTEPS);
    const float* base = x + ((long)(b * TSTEPS + t) * CIN) * NPIX + p;
    float v[CIN];
    float s = 0.f;
    #pragma unroll
    for (int c = 0; c < CIN; c++) { v[c] = base[c * NPIX]; s += v[c]; }
    float mu = s * (1.f / CIN);
    float q = 0.f;
    #pragma unroll
    for (int c = 0; c < CIN; c++) { float d = v[c] - mu; q += d * d; }
    float rs = rsqrtf(q * (1.f / CIN) + 1e-5f);
    int py = p / SP, px = p - py * SP;
    uint32_t* ob = xn + ((long)(t * BATCH + b) * (CIN + 1)) * PPLANE
                      + (py + 1) * PW + px + 1;
    #pragma unroll
    for (int c = 0; c < CIN; c++) ob[c * PPLANE] = pack_hl((v[c] - mu) * rs * gamma[c] + beta[c]);
}

// ---------------- merged prep: weight hi/lo conversion + tap tables ----------------
// perm (LSTM, 8 N-warps): GEMM row o -> orig channel gate*64 + unit,
//   gate=(o>>3)&3, unit=(o>>5)*8 + (o&7)
__device__ __forceinline__ void wconv(const float* W, __nv_bfloat16* hi, __nv_bfloat16* lo,
                                      int i, int Ktot, int Kpad, int perm) {
    int o = i / Kpad, k = i - o * Kpad;
    int orig = perm ? (((o >> 3) & 3) * 64 + (o >> 5) * 8 + (o & 7)) : o;
    float v = (k < Ktot) ? W[(long)orig * Ktot + k] : 0.f;
    __nv_bfloat16 h = __float2bfloat16(v);
    hi[i] = h;
    lo[i] = __float2bfloat16(v - __bfloat162float(h));
}
// tap: {plane-relative byte-free offset (elements), source select}; k >= Ktot
// points at in0's always-zero plane (index C0).
__device__ __forceinline__ int2 tap_make(int j, int Ktot, int C0) {
    if (j >= Ktot) return make_int2(C0 * PPLANE, 0);
    int cc = j / 9, r = j - cc * 9;
    int ky = r / 3 - 1, kx = r - (r / 3) * 3 - 1;
    int sel = cc >= C0;
    int c = sel ? cc - C0 : cc;
    return make_int2(c * PPLANE + ky * PW + kx, sel);
}
__global__ void prep_kernel(const float* w0, const float* w1, const float* wc) {
    const int S0 = GATES * K0PAD, S1 = GATES * K1PAD, S2 = HID * KCPAD;
    int i = blockIdx.x * blockDim.x + threadIdx.x;
    if (i < S0) { wconv(w0, g_w0h, g_w0l, i, K0TOT, K0PAD, 1); return; }
    i -= S0;
    if (i < S1) { wconv(w1, g_w1h, g_w1l, i, K1TOT, K1PAD, 1); return; }
    i -= S1;
    if (i < S2) { wconv(wc, g_wch, g_wcl, i, KCTOT, KCPAD, 0); return; }
    i -= S2;
    if (i < K0PAD) { g_tap0[i] = tap_make(i, K0TOT, CIN); return; }
    i -= K0PAD;
    if (i < K1PAD) { g_tap1[i] = tap_make(i, K1TOT, HID); return; }
    i -= K1PAD;
    if (i < KCPAD) { g_tapc[i] = tap_make(i, KCTOT, HID); return; }
}

// ---------------- pipelined mma.sync implicit-GEMM conv (+fused epilogue) ----------------
// CTA: M=128 pixels x NCH=NWN*32 channels; warps (2 M) x (NWN N); warp tile 64x32.
// Branch-free gather from zero-bordered padded planes; taps in smem.
// bf16 3-term split; term-major MMA order; h-half stagger by wn parity.
// EPI=0 (NWN=8, 512 thr): fused LSTM gates, h padded-plane out, c pixel-major.
// EPI=1 (NWN=2, 128 thr): bias+relu, fp32 unpadded plane-major out.
template<int NWN, int EPI>
__global__ __launch_bounds__(NWN * 64, 1)
void convmma_kernel(const uint32_t* __restrict__ in0, int C0,
                    const uint32_t* __restrict__ in1, int C1,
                    const int2* __restrict__ tap,
                    const __nv_bfloat16* __restrict__ Whi,
                    const __nv_bfloat16* __restrict__ Wlo,
                    int Kpad,
                    const float* __restrict__ bias,
                    void* __restrict__ out_h_, float* __restrict__ out_c) {
    constexpr int NTH = NWN * 64;
    constexpr int NCH = NWN * 32;
    constexpr int APLANE = 128 * 64;        // one bf16 plane: 128 rows x 32 k x 2B
    constexpr int BPLANE = NCH * 64;
    constexpr int BUF = 2 * APLANE + 2 * BPLANE;
    constexpr int AE = 4096 / NTH;          // packed A elems per thread per stage
    constexpr int KST = NTH / 128;

    extern __shared__ char smem[];
    const uint32_t sb = smem_u32(smem);
    int2* tapS = (int2*)(smem + 2 * BUF);
    float* cs = (float*)(smem + 2 * BUF + TAPSZ);                       // [128][68]
    uint32_t* hs = (uint32_t*)(smem + 2 * BUF + TAPSZ + 128 * 68 * 4);  // [128][66]

    const int tid = threadIdx.x;
    const int l = tid & 31;
    const int wid = tid >> 5;
    const int wm = wid & 1;
    const int wn = wid >> 1;
    const int img = blockIdx.y;
    const int pix0 = blockIdx.x * 128;

    const int arow = tid & 127;
    const int ap = pix0 + arow;
    const int apc = ap < NPIX ? ap : NPIX - 1;      // clamp; extra rows unused
    const int apy = apc / SP;
    const int apx = apc - apy * SP;
    const int papd = (apy + 1) * PW + apx + 1;      // padded-plane pixel offset
    const int kbase = tid >> 7;

    const uint32_t* in0i = in0 + (long)img * (C0 + 1) * PPLANE;
    const uint32_t* in1i = in1 + (long)img * (C1 + 1) * PPLANE;

    const int nstage = Kpad >> 5;

    uint32_t ar[AE];

    auto ldgA = [&](int s) {
        const int k0 = s << 5;
        #pragma unroll
        for (int e = 0; e < AE; e++) {
            int k = k0 + kbase + e * KST;
            int2 t = tapS[k];
            const uint32_t* base = t.y ? in1i : in0i;
            ar[e] = __ldg(base + t.x + papd);       // branch-free: borders are zero
        }
    };
    auto stsA = [&](int s) {
        char* buf = smem + (s & 1) * BUF;
        #pragma unroll
        for (int e = 0; e < AE; e++) {
            int k = kbase + e * KST;
            int off = swz(arow, k * 2);
            *(uint16_t*)(buf + off) = (uint16_t)(ar[e] >> 16);
            *(uint16_t*)(buf + APLANE + off) = (uint16_t)(ar[e] & 0xffffu);
        }
    };
    auto cpB = [&](int s) {
        const uint32_t bb = sb + (s & 1) * BUF + 2 * APLANE;
        const int k0 = s << 5;
        const __nv_bfloat16* wh = Whi + k0;
        const __nv_bfloat16* wl = Wlo + k0;
        #pragma unroll
        for (int i = 0; i < NCH * 4 / NTH; i++) {
            int idx = tid + i * NTH;
            int n = idx >> 2, j = idx & 3;
            long wr = (long)n * Kpad + j * 8;
            int off = swz(n, j * 16);
            cp_async16(bb + off, wh + wr);
            cp_async16(bb + BPLANE + off, wl + wr);
        }
        CP_COMMIT();
    };

    float acc[4][4][4];
    #pragma unroll
    for (int a = 0; a < 4; a++)
        #pragma unroll
        for (int b = 0; b < 4; b++)
            #pragma unroll
            for (int c = 0; c < 4; c++) acc[a][b][c] = 0.f;

    // ---- prologue ----
    for (int i = tid; i < Kpad; i += NTH) tapS[i] = tap[i];   // taps -> smem once
    cpB(0);
    if (EPI == 0) {
        #pragma unroll
        for (int i = 0; i < 2048 / NTH; i++) {
            int idx4 = tid + i * NTH;
            int p = idx4 >> 4, jq = idx4 & 15;
            int pg = pix0 + p;
            float4 v = make_float4(0.f, 0.f, 0.f, 0.f);
            if (pg < NPIX)
                v = *(const float4*)(out_c + ((long)img * NPIX + pg) * 64 + jq * 4);
            *(float4*)(cs + p * 68 + jq * 4) = v;
        }
    }
    __syncthreads();          // taps visible to all before ldgA
    ldgA(0);
    stsA(0);
    ldgA(1);
    CP_WAIT(0);
    __syncthreads();

    for (int s = 0; s < nstage; s++) {
        if (s + 1 < nstage) cpB(s + 1);   // into buffer released at prev barrier

        const uint32_t cur = sb + (s & 1) * BUF;
        const uint32_t sAh = cur, sAl = cur + APLANE;
        const uint32_t sBh = cur + 2 * APLANE, sBl = sBh + BPLANE;

        #pragma unroll
        for (int h2 = 0; h2 < 2; h2++) {
            const int h = h2 ^ (wn & 1);          // stagger halves across warps
            uint32_t bh[2][4], bl[2][4];
            const int brow = wn * 32 + ((l >> 4) & 1) * 8 + (l & 7);
            const int bko = (h * 16 + ((l >> 3) & 1) * 8) * 2;
            #pragma unroll
            for (int nf2 = 0; nf2 < 2; nf2++) {
                LDSM4(bh[nf2], sBh + swz(brow + nf2 * 16, bko));
                LDSM4(bl[nf2], sBl + swz(brow + nf2 * 16, bko));
            }
            const int aro = wm * 64 + (l & 15);
            const int ako = (h * 16 + (l >> 4) * 8) * 2;
            #pragma unroll
            for (int mfp = 0; mfp < 2; mfp++) {
                uint32_t ah[2][4], al[2][4];
                #pragma unroll
                for (int mi = 0; mi < 2; mi++) {
                    int mf = mfp * 2 + mi;
                    LDSM4(ah[mi], sAh + swz(aro + mf * 16, ako));
                    LDSM4(al[mi], sAl + swz(aro + mf * 16, ako));
                }
                #pragma unroll
                for (int mi = 0; mi < 2; mi++)
                    #pragma unroll
                    for (int nf = 0; nf < 4; nf++)
                        mma_bf16(acc[mfp * 2 + mi][nf], ah[mi], &bh[nf >> 1][(nf & 1) * 2]);
                #pragma unroll
                for (int mi = 0; mi < 2; mi++)
                    #pragma unroll
                    for (int nf = 0; nf < 4; nf++)
                        mma_bf16(acc[mfp * 2 + mi][nf], ah[mi], &bl[nf >> 1][(nf & 1) * 2]);
                #pragma unroll
                for (int mi = 0; mi < 2; mi++)
                    #pragma unroll
                    for (int nf = 0; nf < 4; nf++)
                        mma_bf16(acc[mfp * 2 + mi][nf], al[mi], &bh[nf >> 1][(nf & 1) * 2]);
            }
        }
        if (s + 1 < nstage) stsA(s + 1);
        if (s + 2 < nstage) ldgA(s + 2);
        CP_WAIT(0);
        __syncthreads();
    }

    if (EPI == 0) {
        #pragma unroll
        for (int mf = 0; mf < 4; mf++) {
            #pragma unroll
            for (int c = 0; c < 4; c++) {
                int p = wm * 64 + mf * 16 + (l >> 2) + ((c >> 1) & 1) * 8;
                int j = wn * 8 + (l & 3) * 2 + (c & 1);
                float zi = acc[mf][0][c] + __ldg(bias + j);
                float zf = acc[mf][1][c] + __ldg(bias + 64 + j);
                float zo = acc[mf][2][c] + __ldg(bias + 128 + j);
                float zg = acc[mf][3][c] + __ldg(bias + 192 + j);
                if (pix0 + p < NPIX) {
                    float ig = sigm(zi), fg = sigm(zf), og = sigm(zo);
                    float gg = tanh_acc(zg);
                    float cn = fg * cs[p * 68 + j] + ig * gg;
                    cs[p * 68 + j] = cn;
                    hs[p * 66 + j] = pack_hl(og * tanh_acc(cn));
                }
            }
        }
        __syncthreads();
        uint32_t* out_h = (uint32_t*)out_h_;
        #pragma unroll
        for (int i = 0; i < 2048 / NTH; i++) {
            int idx4 = tid + i * NTH;
            int p = idx4 >> 4, jq = idx4 & 15;
            int pg = pix0 + p;
            if (pg < NPIX)
                *(float4*)(out_c + ((long)img * NPIX + pg) * 64 + jq * 4) =
                    *(const float4*)(cs + p * 68 + jq * 4);
        }
        #pragma unroll
        for (int uu = 0; uu < 64 * 32 / NTH; uu++) {   // 64 units
            int unit = wid + (NTH / 32) * uu;
            #pragma unroll
            for (int i = 0; i < 4; i++) {
                int px = i * 32 + l;
                int pg = pix0 + px;
                if (pg < NPIX) {
                    int gy = pg / SP, gx = pg - gy * SP;
                    out_h[((long)img * (HID + 1) + unit) * PPLANE + (gy + 1) * PW + gx + 1]
                        = hs[px * 66 + unit];
                }
            }
        }
    } else {
        float* out_h = (float*)out_h_;
        #pragma unroll
        for (int mf = 0; mf < 4; mf++) {
            #pragma unroll
            for (int c = 0; c < 4; c++) {
                int p = pix0 + wm * 64 + mf * 16 + (l >> 2) + ((c >> 1) & 1) * 8;
                #pragma unroll
                for (int nf = 0; nf < 4; nf++) {
                    int n = wn * 32 + nf * 8 + (l & 3) * 2 + (c & 1);
                    float v = acc[mf][nf][c] + __ldg(bias + n);
                    if (p < NPIX)
                        out_h[((long)img * HID + n) * NPIX + p] = fmaxf(v, 0.f);
                }
            }
        }
    }
}

// ---------------- maxpool 2x2 stride 2 ----------------
__global__ void pool_kernel(const float* __restrict__ y, float* __restrict__ out) {
    int idx = blockIdx.x * blockDim.x + threadIdx.x;
    if (idx >= BATCH * HID * POOLD * POOLD) return;
    int j = idx % POOLD;
    int i = (idx / POOLD) % POOLD;
    int ch = (idx / (POOLD * POOLD)) % HID;
    int b = idx / (POOLD * POOLD * HID);
    const float* p = y + ((long)(b * HID + ch)) * NPIX + (2 * i) * SP + 2 * j;
    float m = fmaxf(fmaxf(p[0], p[1]), fmaxf(p[SP], p[SP + 1]));
    out[(long)b * FEAT + ch * (POOLD * POOLD) + i * POOLD + j] = m;
}

// ---------------- FC: one warp per output element ----------------
__global__ void fc_kernel(const float* __restrict__ in, const float* __restrict__ w,
                          const float* __restrict__ b, float* __restrict__ out,
                          int M, int N, int K, int relu) {
    int warp = (blockIdx.x * blockDim.x + threadIdx.x) >> 5;
    int lane = threadIdx.x & 31;
    if (warp >= M * N) return;
    int m = warp / N, n = warp - m * N;
    const float* ir = in + (long)m * K;
    const float* wr = w + (long)n * K;
    float s = 0.f;
    for (int k = lane; k < K; k += 32) s += ir[k] * wr[k];
    #pragma unroll
    for (int o = 16; o; o >>= 1) s += __shfl_xor_sync(0xFFFFFFFFu, s, o);
    if (lane == 0) {
        s += b[n];
        if (relu) s = fmaxf(s, 0.f);
        out[(long)m * N + n] = s;
    }
}

__global__ void lsm_kernel(const float* __restrict__ in, float* __restrict__ out) {
    int m = blockIdx.x * blockDim.x + threadIdx.x;
    if (m >= BATCH) return;
    float a = in[2 * m], b = in[2 * m + 1];
    float mx = fmaxf(a, b);
    float l = mx + logf(expf(a - mx) + expf(b - mx));
    out[2 * m] = a - l;
    out[2 * m + 1] = b - l;
}

// ---------------- launch ----------------
extern "C" void kernel_launch(void* const* d_in, const int* in_sizes, int n_in,
                              void* d_out, int out_size) {
    const float* x   = (const float*)d_in[0];
    const float* lg  = (const float*)d_in[1];
    const float* lb  = (const float*)d_in[2];
    const float* w0  = (const float*)d_in[3];
    const float* b0  = (const float*)d_in[4];
    const float* w1  = (const float*)d_in[5];
    const float* b1  = (const float*)d_in[6];
    const float* wc  = (const float*)d_in[7];
    const float* bc  = (const float*)d_in[8];
    const float* wf1 = (const float*)d_in[9];
    const float* bf1 = (const float*)d_in[10];
    const float* wf2 = (const float*)d_in[11];
    const float* bf2 = (const float*)d_in[12];
    const float* wf3 = (const float*)d_in[13];
    const float* bf3 = (const float*)d_in[14];
    float* out = (float*)d_out;

    uint32_t *xn, *h0a, *h0b, *h1a, *h1b;
    float *c0, *c1, *y, *pool, *f1, *f2, *f3;
    __nv_bfloat16 *w0h, *w0l, *w1h, *w1l, *wch, *wcl;
    int2 *tap0, *tap1, *tapc;
    cudaGetSymbolAddress((void**)&xn,  g_xn);
    cudaGetSymbolAddress((void**)&h0a, g_h0a);
    cudaGetSymbolAddress((void**)&h0b, g_h0b);
    cudaGetSymbolAddress((void**)&h1a, g_h1a);
    cudaGetSymbolAddress((void**)&h1b, g_h1b);
    cudaGetSymbolAddress((void**)&c0,  g_c0);
    cudaGetSymbolAddress((void**)&c1,  g_c1);
    cudaGetSymbolAddress((void**)&y,   g_y);
    cudaGetSymbolAddress((void**)&pool, g_pool);
    cudaGetSymbolAddress((void**)&f1, g_f1);
    cudaGetSymbolAddress((void**)&f2, g_f2);
    cudaGetSymbolAddress((void**)&f3, g_f3);
    cudaGetSymbolAddress((void**)&w0h, g_w0h);
    cudaGetSymbolAddress((void**)&w0l, g_w0l);
    cudaGetSymbolAddress((void**)&w1h, g_w1h);
    cudaGetSymbolAddress((void**)&w1l, g_w1l);
    cudaGetSymbolAddress((void**)&wch, g_wch);
    cudaGetSymbolAddress((void**)&wcl, g_wcl);
    cudaGetSymbolAddress((void**)&tap0, g_tap0);
    cudaGetSymbolAddress((void**)&tap1, g_tap1);
    cudaGetSymbolAddress((void**)&tapc, g_tapc);

    const int BUF0 = 2 * 128 * 64 + 2 * 256 * 64;
    const int SMEM0 = 2 * BUF0 + TAPSZ + 128 * 68 * 4 + 128 * 66 * 4;   // 176128
    const int BUF1 = 2 * 128 * 64 + 2 * 64 * 64;
    const int SMEM1 = 2 * BUF1 + TAPSZ;                                 // 58368
    cudaFuncSetAttribute(convmma_kernel<8, 0>, cudaFuncAttributeMaxDynamicSharedMemorySize, SMEM0);
    cudaFuncSetAttribute(convmma_kernel<2, 1>, cudaFuncAttributeMaxDynamicSharedMemorySize, SMEM1);

    zero_all_kernel<<<(int)((NXZ + 255) / 256), 256>>>(xn, h0a, h0b, h1a, h1b, c0, c1);

    const int nln = BATCH * TSTEPS * NPIX;
    ln_kernel<<<(nln + 255) / 256, 256>>>(x, lg, lb, xn);

    const int nprep = GATES * K0PAD + GATES * K1PAD + HID * KCPAD + K0PAD + K1PAD + KCPAD;
    prep_kernel<<<(nprep + 255) / 256, 256>>>(w0, w1, wc);

    uint32_t* h0buf[2] = {h0a, h0b};
    uint32_t* h1buf[2] = {h1a, h1b};
    dim3 grid0(5, BATCH);
    for (int t = 0; t < TSTEPS; t++) {
        int r = t & 1;
        const uint32_t* xt = xn + (long)t * BATCH * (CIN + 1) * PPLANE;
        convmma_kernel<8, 0><<<grid0, 512, SMEM0>>>(
            xt, CIN, h0buf[r], HID, tap0, w0h, w0l, K0PAD, b0, h0buf[1 - r], c0);
        convmma_kernel<8, 0><<<grid0, 512, SMEM0>>>(
            h0buf[1 - r], HID, h1buf[r], HID, tap1, w1h, w1l, K1PAD, b1, h1buf[1 - r], c1);
    }
    const uint32_t* hfin = h1buf[0];   // t=19 (r=1) wrote h1buf[0]

    dim3 grid1(5, BATCH);
    convmma_kernel<2, 1><<<grid1, 128, SMEM1>>>(
        hfin, HID, hfin, HID, tapc, wch, wcl, KCPAD, bc, y, (float*)0);

    const int npool = BATCH * HID * POOLD * POOLD;
    pool_kernel<<<(npool + 255) / 256, 256>>>(y, pool);
    {
        int warps = BATCH * FC1N;
        fc_kernel<<<(warps * 32 + 255) / 256, 256>>>(pool, wf1, bf1, f1, BATCH, FC1N, FEAT, 1);
    }
    {
        int warps = BATCH * FC2N;
        fc_kernel<<<(warps * 32 + 255) / 256, 256>>>(f1, wf2, bf2, f2, BATCH, FC2N, FC1N, 1);
    }
    {
        int warps = BATCH * 2;
        fc_kernel<<<(warps * 32 + 255) / 256, 256>>>(f2, wf3, bf3, f3, BATCH, 2, FC2N, 0);
    }
    lsm_kernel<<<1, BATCH>>>(f3, out);
}

// round 11
// speedup vs baseline: 4.0571x; 1.1532x over previous
#include <cuda_runtime.h>
#include <cuda_bf16.h>
#include <math.h>
#include <cstdint>

// ---------------- problem constants ----------------
#define BATCH 64
#define TSTEPS 20
#define CIN 25
#define HID 64
#define SP 25
#define NPIX 625
#define GATES 256
#define POOLD 12
#define FEAT 9216
#define FC1N 128
#define FC2N 64

#define PW 27                 // padded plane width (25 + border)
#define PPLANE 729            // 27*27

#define K0TOT ((CIN + HID) * 9)   // 801
#define K0PAD 832                 // 26 stages of 32
#define K1TOT (2 * HID * 9)       // 1152
#define K1PAD 1152                // 36 stages
#define KCTOT (HID * 9)           // 576
#define KCPAD 576                 // 18 stages
#define TAPSZ 9216                // 1152 * sizeof(int2)

// ---------------- scratch (device globals, no allocation) ----------------
// activations packed u32 = (bf16 hi << 16) | bf16 lo, in 27x27 zero-bordered
// planes; each image has one extra always-zero plane at channel index C.
__device__ __align__(16) uint32_t g_xn[(long)TSTEPS * BATCH * (CIN + 1) * PPLANE];
__device__ __align__(16) uint32_t g_h0a[(long)BATCH * (HID + 1) * PPLANE];
__device__ __align__(16) uint32_t g_h0b[(long)BATCH * (HID + 1) * PPLANE];
__device__ __align__(16) uint32_t g_h1a[(long)BATCH * (HID + 1) * PPLANE];
__device__ __align__(16) uint32_t g_h1b[(long)BATCH * (HID + 1) * PPLANE];
__device__ __align__(16) float g_c0[(long)BATCH * NPIX * HID];
__device__ __align__(16) float g_c1[(long)BATCH * NPIX * HID];
__device__ __align__(16) float g_y [(long)BATCH * HID * NPIX];
__device__ __align__(16) float g_pool[(long)BATCH * FEAT];
__device__ float g_f1[BATCH * FC1N];
__device__ float g_f2[BATCH * FC2N];
__device__ float g_f3[BATCH * 2];
__device__ __align__(16) __nv_bfloat16 g_w0h[GATES * K0PAD];
__device__ __align__(16) __nv_bfloat16 g_w0l[GATES * K0PAD];
__device__ __align__(16) __nv_bfloat16 g_w1h[GATES * K1PAD];
__device__ __align__(16) __nv_bfloat16 g_w1l[GATES * K1PAD];
__device__ __align__(16) __nv_bfloat16 g_wch[HID * KCPAD];
__device__ __align__(16) __nv_bfloat16 g_wcl[HID * KCPAD];
__device__ __align__(16) int2 g_tap0[K0PAD];
__device__ __align__(16) int2 g_tap1[K1PAD];
__device__ __align__(16) int2 g_tapc[KCPAD];

// ---------------- helpers ----------------
__device__ __forceinline__ uint32_t smem_u32(const void* p) {
    uint32_t a;
    asm("{ .reg .u64 t; cvta.to.shared.u64 t, %1; cvt.u32.u64 %0, t; }" : "=r"(a) : "l"(p));
    return a;
}
#define LDSM4(r, a) \
    asm volatile("ldmatrix.sync.aligned.m8n8.x4.shared.b16 {%0,%1,%2,%3}, [%4];" \
        : "=r"((r)[0]), "=r"((r)[1]), "=r"((r)[2]), "=r"((r)[3]) : "r"(a))

__device__ __forceinline__ void mma_bf16(float* c, const uint32_t* a, const uint32_t* b) {
    asm volatile(
        "mma.sync.aligned.m16n8k16.row.col.f32.bf16.bf16.f32 "
        "{%0,%1,%2,%3}, {%4,%5,%6,%7}, {%8,%9}, {%0,%1,%2,%3};"
        : "+f"(c[0]), "+f"(c[1]), "+f"(c[2]), "+f"(c[3])
        : "r"(a[0]), "r"(a[1]), "r"(a[2]), "r"(a[3]), "r"(b[0]), "r"(b[1]));
}
__device__ __forceinline__ void cp_async16(uint32_t dst, const void* src) {
    asm volatile("cp.async.cg.shared.global [%0], [%1], 16;" :: "r"(dst), "l"(src));
}
#define CP_COMMIT() asm volatile("cp.async.commit_group;" ::: "memory")
#define CP_WAIT(n)  asm volatile("cp.async.wait_group %0;" :: "n"(n) : "memory")

__device__ __forceinline__ float sigm(float x) { return 1.f / (1.f + __expf(-x)); }
__device__ __forceinline__ float tanh_acc(float x) {
    float e = __expf(-2.f * fabsf(x));
    float t = (1.f - e) / (1.f + e);
    return copysignf(t, x);
}
__device__ __forceinline__ uint32_t pack_hl(float v) {
    __nv_bfloat16 h = __float2bfloat16(v);
    float hf = __bfloat162float(h);
    __nv_bfloat16 lo = __float2bfloat16(v - hf);
    return ((uint32_t)__bfloat16_as_ushort(h) << 16) | (uint32_t)__bfloat16_as_ushort(lo);
}
__device__ __forceinline__ int swz(int row, int kbyte) {
    return row * 64 + (kbyte ^ (((row >> 1) & 3) << 4));
}

// ---------------- zero all recurrent/padded state ----------------
#define NXZ ((long)TSTEPS * BATCH * (CIN + 1) * PPLANE)
#define NHZ ((long)BATCH * (HID + 1) * PPLANE)
#define NCZ ((long)BATCH * NPIX * HID)
__global__ void zero_all_kernel(uint32_t* xn, uint32_t* h0a, uint32_t* h0b,
                                uint32_t* h1a, uint32_t* h1b, float* c0, float* c1) {
    long i = (long)blockIdx.x * blockDim.x + threadIdx.x;
    if (i < NXZ) xn[i] = 0u;
    if (i < NHZ) { h0a[i] = 0u; h0b[i] = 0u; h1a[i] = 0u; h1b[i] = 0u; }
    if (i < NCZ) { c0[i] = 0.f; c1[i] = 0.f; }
}

// ---------------- LayerNorm -> padded planes ----------------
__global__ void ln_kernel(const float* __restrict__ x,
                          const float* __restrict__ gamma,
                          const float* __restrict__ beta,
                          uint32_t* __restrict__ xn) {
    int idx = blockIdx.x * blockDim.x + threadIdx.x;
    if (idx >= BATCH * TSTEPS * NPIX) return;
    int p = idx % NPIX;
    int t = (idx / NPIX) % TSTEPS;
    int b = idx / (NPIX * TSTEPS);
    const float* base = x + ((long)(b * TSTEPS + t) * CIN) * NPIX + p;
    float v[CIN];
    float s = 0.f;
    #pragma unroll
    for (int c = 0; c < CIN; c++) { v[c] = base[c * NPIX]; s += v[c]; }
    float mu = s * (1.f / CIN);
    float q = 0.f;
    #pragma unroll
    for (int c = 0; c < CIN; c++) { float d = v[c] - mu; q += d * d; }
    float rs = rsqrtf(q * (1.f / CIN) + 1e-5f);
    int py = p / SP, px = p - py * SP;
    uint32_t* ob = xn + ((long)(t * BATCH + b) * (CIN + 1)) * PPLANE
                      + (py + 1) * PW + px + 1;
    #pragma unroll
    for (int c = 0; c < CIN; c++) ob[c * PPLANE] = pack_hl((v[c] - mu) * rs * gamma[c] + beta[c]);
}

// ---------------- merged prep: weight hi/lo conversion + tap tables ----------------
// perm (LSTM, NCH=128 CTAs, nblk in bit 7): GEMM row o -> orig channel
//   gate*64 + nblk*32 + wn*8 + r, gate=(o>>3)&3, wn=(o>>5)&3, nblk=(o>>7)&1.
__device__ __forceinline__ void wconv(const float* W, __nv_bfloat16* hi, __nv_bfloat16* lo,
                                      int i, int Ktot, int Kpad, int perm) {
    int o = i / Kpad, k = i - o * Kpad;
    int orig = perm ? (((o >> 3) & 3) * 64 + ((o >> 7) & 1) * 32 + ((o >> 5) & 3) * 8 + (o & 7)) : o;
    float v = (k < Ktot) ? W[(long)orig * Ktot + k] : 0.f;
    __nv_bfloat16 h = __float2bfloat16(v);
    hi[i] = h;
    lo[i] = __float2bfloat16(v - __bfloat162float(h));
}
// tap: {plane-relative element offset, source select}; k >= Ktot -> zero plane.
__device__ __forceinline__ int2 tap_make(int j, int Ktot, int C0) {
    if (j >= Ktot) return make_int2(C0 * PPLANE, 0);
    int cc = j / 9, r = j - cc * 9;
    int ky = r / 3 - 1, kx = r - (r / 3) * 3 - 1;
    int sel = cc >= C0;
    int c = sel ? cc - C0 : cc;
    return make_int2(c * PPLANE + ky * PW + kx, sel);
}
__global__ void prep_kernel(const float* w0, const float* w1, const float* wc) {
    const int S0 = GATES * K0PAD, S1 = GATES * K1PAD, S2 = HID * KCPAD;
    int i = blockIdx.x * blockDim.x + threadIdx.x;
    if (i < S0) { wconv(w0, g_w0h, g_w0l, i, K0TOT, K0PAD, 1); return; }
    i -= S0;
    if (i < S1) { wconv(w1, g_w1h, g_w1l, i, K1TOT, K1PAD, 1); return; }
    i -= S1;
    if (i < S2) { wconv(wc, g_wch, g_wcl, i, KCTOT, KCPAD, 0); return; }
    i -= S2;
    if (i < K0PAD) { g_tap0[i] = tap_make(i, K0TOT, CIN); return; }
    i -= K0PAD;
    if (i < K1PAD) { g_tap1[i] = tap_make(i, K1TOT, HID); return; }
    i -= K1PAD;
    if (i < KCPAD) { g_tapc[i] = tap_make(i, KCTOT, HID); return; }
}

// ---------------- pipelined mma.sync implicit-GEMM conv (+fused epilogue) ----------------
// CTA: M=128 pixels x NCH=NWN*32 channels; warps (2 M) x (NWN N); warp tile 64x32.
// Branch-free gather from zero-bordered padded planes; taps in smem; paired STS.32.
// EPI=0 (NWN=4, 256 thr, 2 CTAs/SM, blockIdx.z = nblk): fused LSTM gates for 32
//   hidden units, h padded-plane out, c pixel-major in/out via smem staging.
// EPI=1 (NWN=2, 128 thr): bias+relu, fp32 unpadded plane-major out.
template<int NWN, int EPI>
__global__ __launch_bounds__(NWN * 64, 2)
void convmma_kernel(const uint32_t* __restrict__ in0, int C0,
                    const uint32_t* __restrict__ in1, int C1,
                    const int2* __restrict__ tap,
                    const __nv_bfloat16* __restrict__ Whi,
                    const __nv_bfloat16* __restrict__ Wlo,
                    int Kpad,
                    const float* __restrict__ bias,
                    void* __restrict__ out_h_, float* __restrict__ out_c) {
    constexpr int NTH = NWN * 64;
    constexpr int NCH = NWN * 32;
    constexpr int APLANE = 128 * 64;        // one bf16 plane: 128 rows x 32 k x 2B
    constexpr int BPLANE = NCH * 64;
    constexpr int BUF = 2 * APLANE + 2 * BPLANE;
    constexpr int AE = 4096 / NTH;          // packed A elems per thread per stage

    extern __shared__ char smem[];
    const uint32_t sb = smem_u32(smem);
    int2* tapS = (int2*)(smem + 2 * BUF);
    float* cs = (float*)(smem + 2 * BUF + TAPSZ);                       // [128][36]
    uint32_t* hs = (uint32_t*)(smem + 2 * BUF + TAPSZ + 128 * 36 * 4);  // [128][33]

    const int tid = threadIdx.x;
    const int l = tid & 31;
    const int wid = tid >> 5;
    const int wm = wid & 1;
    const int wn = wid >> 1;
    const int img = blockIdx.y;
    const int pix0 = blockIdx.x * 128;
    const int nblk = blockIdx.z;
    const int nbase = nblk * NCH;

    const int arow = tid & 127;
    const int ap = pix0 + arow;
    const int apc = ap < NPIX ? ap : NPIX - 1;
    const int apy = apc / SP;
    const int apx = apc - apy * SP;
    const int papd = (apy + 1) * PW + apx + 1;
    const int kbase = tid >> 7;             // 0..(NTH/128 - 1)

    const uint32_t* in0i = in0 + (long)img * (C0 + 1) * PPLANE;
    const uint32_t* in1i = in1 + (long)img * (C1 + 1) * PPLANE;

    const int nstage = Kpad >> 5;

    uint32_t ar[AE];

    auto ldgA = [&](int s) {
        const int k0 = s << 5;
        #pragma unroll
        for (int e = 0; e < AE; e++) {
            int k = kbase * AE + e;
            int2 t = tapS[k0 + k];
            const uint32_t* base = t.y ? in1i : in0i;
            ar[e] = __ldg(base + t.x + papd);
        }
    };
    auto stsA = [&](int s) {
        char* buf = smem + (s & 1) * BUF;
        #pragma unroll
        for (int e = 0; e < AE; e += 2) {
            int k = kbase * AE + e;
            int off = swz(arow, k * 2);
            uint32_t hi2 = (ar[e] >> 16) | (ar[e + 1] & 0xffff0000u);
            uint32_t lo2 = (ar[e] & 0xffffu) | (ar[e + 1] << 16);
            *(uint32_t*)(buf + off) = hi2;
            *(uint32_t*)(buf + APLANE + off) = lo2;
        }
    };
    auto cpB = [&](int s) {
        const uint32_t bb = sb + (s & 1) * BUF + 2 * APLANE;
        const int k0 = s << 5;
        const __nv_bfloat16* wh = Whi + k0;
        const __nv_bfloat16* wl = Wlo + k0;
        #pragma unroll
        for (int i = 0; i < NCH * 4 / NTH; i++) {
            int idx = tid + i * NTH;
            int n = idx >> 2, j = idx & 3;
            long wr = (long)(nbase + n) * Kpad + j * 8;
            int off = swz(n, j * 16);
            cp_async16(bb + off, wh + wr);
            cp_async16(bb + BPLANE + off, wl + wr);
        }
        CP_COMMIT();
    };

    float acc[4][4][4];
    #pragma unroll
    for (int a = 0; a < 4; a++)
        #pragma unroll
        for (int b = 0; b < 4; b++)
            #pragma unroll
            for (int c = 0; c < 4; c++) acc[a][b][c] = 0.f;

    // ---- prologue ----
    for (int i = tid; i < Kpad; i += NTH) tapS[i] = tap[i];
    cpB(0);
    if (EPI == 0) {
        #pragma unroll
        for (int i = 0; i < 1024 / NTH; i++) {
            int idx4 = tid + i * NTH;
            int p = idx4 >> 3, jq = idx4 & 7;
            int pg = pix0 + p;
            float4 v = make_float4(0.f, 0.f, 0.f, 0.f);
            if (pg < NPIX)
                v = *(const float4*)(out_c + ((long)img * NPIX + pg) * 64 + nblk * 32 + jq * 4);
            *(float4*)(cs + p * 36 + jq * 4) = v;
        }
    }
    __syncthreads();          // taps visible
    ldgA(0);
    stsA(0);
    ldgA(1);
    CP_WAIT(0);
    __syncthreads();

    for (int s = 0; s < nstage; s++) {
        if (s + 1 < nstage) cpB(s + 1);   // buffer released at prev barrier

        const uint32_t cur = sb + (s & 1) * BUF;
        const uint32_t sAh = cur, sAl = cur + APLANE;
        const uint32_t sBh = cur + 2 * APLANE, sBl = sBh + BPLANE;

        #pragma unroll
        for (int h = 0; h < 2; h++) {
            uint32_t bh[2][4], bl[2][4];
            const int brow = wn * 32 + ((l >> 4) & 1) * 8 + (l & 7);
            const int bko = (h * 16 + ((l >> 3) & 1) * 8) * 2;
            #pragma unroll
            for (int nf2 = 0; nf2 < 2; nf2++) {
                LDSM4(bh[nf2], sBh + swz(brow + nf2 * 16, bko));
                LDSM4(bl[nf2], sBl + swz(brow + nf2 * 16, bko));
            }
            const int aro = wm * 64 + (l & 15);
            const int ako = (h * 16 + (l >> 4) * 8) * 2;
            #pragma unroll
            for (int mf = 0; mf < 4; mf++) {
                uint32_t ah[4], al[4];
                LDSM4(ah, sAh + swz(aro + mf * 16, ako));
                LDSM4(al, sAl + swz(aro + mf * 16, ako));
                #pragma unroll
                for (int nf = 0; nf < 4; nf++) {
                    const uint32_t* bhp = &bh[nf >> 1][(nf & 1) * 2];
                    const uint32_t* blp = &bl[nf >> 1][(nf & 1) * 2];
                    mma_bf16(acc[mf][nf], ah, bhp);
                    mma_bf16(acc[mf][nf], ah, blp);
                    mma_bf16(acc[mf][nf], al, bhp);
                }
            }
        }
        if (s + 1 < nstage) stsA(s + 1);
        if (s + 2 < nstage) ldgA(s + 2);
        CP_WAIT(0);
        __syncthreads();
    }

    if (EPI == 0) {
        #pragma unroll
        for (int mf = 0; mf < 4; mf++) {
            #pragma unroll
            for (int c = 0; c < 4; c++) {
                int p = wm * 64 + mf * 16 + (l >> 2) + ((c >> 1) & 1) * 8;
                int j = wn * 8 + (l & 3) * 2 + (c & 1);
                int u = nblk * 32 + j;
                float zi = acc[mf][0][c] + __ldg(bias + u);
                float zf = acc[mf][1][c] + __ldg(bias + 64 + u);
                float zo = acc[mf][2][c] + __ldg(bias + 128 + u);
                float zg = acc[mf][3][c] + __ldg(bias + 192 + u);
                if (pix0 + p < NPIX) {
                    float ig = sigm(zi), fg = sigm(zf), og = sigm(zo);
                    float gg = tanh_acc(zg);
                    float cn = fg * cs[p * 36 + j] + ig * gg;
                    cs[p * 36 + j] = cn;
                    hs[p * 33 + j] = pack_hl(og * tanh_acc(cn));
                }
            }
        }
        __syncthreads();
        uint32_t* out_h = (uint32_t*)out_h_;
        #pragma unroll
        for (int i = 0; i < 1024 / NTH; i++) {
            int idx4 = tid + i * NTH;
            int p = idx4 >> 3, jq = idx4 & 7;
            int pg = pix0 + p;
            if (pg < NPIX)
                *(float4*)(out_c + ((long)img * NPIX + pg) * 64 + nblk * 32 + jq * 4) =
                    *(const float4*)(cs + p * 36 + jq * 4);
        }
        #pragma unroll
        for (int uu = 0; uu < 32 * 32 / NTH; uu++) {   // 32 units / CTA
            int unit = wid + (NTH / 32) * uu;
            #pragma unroll
            for (int i = 0; i < 4; i++) {
                int px = i * 32 + l;
                int pg = pix0 + px;
                if (pg < NPIX) {
                    int gy = pg / SP, gx = pg - gy * SP;
                    out_h[((long)img * (HID + 1) + nblk * 32 + unit) * PPLANE
                          + (gy + 1) * PW + gx + 1] = hs[px * 33 + unit];
                }
            }
        }
    } else {
        float* out_h = (float*)out_h_;
        #pragma unroll
        for (int mf = 0; mf < 4; mf++) {
            #pragma unroll
            for (int c = 0; c < 4; c++) {
                int p = pix0 + wm * 64 + mf * 16 + (l >> 2) + ((c >> 1) & 1) * 8;
                #pragma unroll
                for (int nf = 0; nf < 4; nf++) {
                    int n = wn * 32 + nf * 8 + (l & 3) * 2 + (c & 1);
                    float v = acc[mf][nf][c] + __ldg(bias + n);
                    if (p < NPIX)
                        out_h[((long)img * HID + n) * NPIX + p] = fmaxf(v, 0.f);
                }
            }
        }
    }
}

// ---------------- maxpool 2x2 stride 2 ----------------
__global__ void pool_kernel(const float* __restrict__ y, float* __restrict__ out) {
    int idx = blockIdx.x * blockDim.x + threadIdx.x;
    if (idx >= BATCH * HID * POOLD * POOLD) return;
    int j = idx % POOLD;
    int i = (idx / POOLD) % POOLD;
    int ch = (idx / (POOLD * POOLD)) % HID;
    int b = idx / (POOLD * POOLD * HID);
    const float* p = y + ((long)(b * HID + ch)) * NPIX + (2 * i) * SP + 2 * j;
    float m = fmaxf(fmaxf(p[0], p[1]), fmaxf(p[SP], p[SP + 1]));
    out[(long)b * FEAT + ch * (POOLD * POOLD) + i * POOLD + j] = m;
}

// ---------------- FC: one warp per output element ----------------
__global__ void fc_kernel(const float* __restrict__ in, const float* __restrict__ w,
                          const float* __restrict__ b, float* __restrict__ out,
                          int M, int N, int K, int relu) {
    int warp = (blockIdx.x * blockDim.x + threadIdx.x) >> 5;
    int lane = threadIdx.x & 31;
    if (warp >= M * N) return;
    int m = warp / N, n = warp - m * N;
    const float* ir = in + (long)m * K;
    const float* wr = w + (long)n * K;
    float s = 0.f;
    for (int k = lane; k < K; k += 32) s += ir[k] * wr[k];
    #pragma unroll
    for (int o = 16; o; o >>= 1) s += __shfl_xor_sync(0xFFFFFFFFu, s, o);
    if (lane == 0) {
        s += b[n];
        if (relu) s = fmaxf(s, 0.f);
        out[(long)m * N + n] = s;
    }
}

__global__ void lsm_kernel(const float* __restrict__ in, float* __restrict__ out) {
    int m = blockIdx.x * blockDim.x + threadIdx.x;
    if (m >= BATCH) return;
    float a = in[2 * m], b = in[2 * m + 1];
    float mx = fmaxf(a, b);
    float l = mx + logf(expf(a - mx) + expf(b - mx));
    out[2 * m] = a - l;
    out[2 * m + 1] = b - l;
}

// ---------------- launch ----------------
extern "C" void kernel_launch(void* const* d_in, const int* in_sizes, int n_in,
                              void* d_out, int out_size) {
    const float* x   = (const float*)d_in[0];
    const float* lg  = (const float*)d_in[1];
    const float* lb  = (const float*)d_in[2];
    const float* w0  = (const float*)d_in[3];
    const float* b0  = (const float*)d_in[4];
    const float* w1  = (const float*)d_in[5];
    const float* b1  = (const float*)d_in[6];
    const float* wc  = (const float*)d_in[7];
    const float* bc  = (const float*)d_in[8];
    const float* wf1 = (const float*)d_in[9];
    const float* bf1 = (const float*)d_in[10];
    const float* wf2 = (const float*)d_in[11];
    const float* bf2 = (const float*)d_in[12];
    const float* wf3 = (const float*)d_in[13];
    const float* bf3 = (const float*)d_in[14];
    float* out = (float*)d_out;

    uint32_t *xn, *h0a, *h0b, *h1a, *h1b;
    float *c0, *c1, *y, *pool, *f1, *f2, *f3;
    __nv_bfloat16 *w0h, *w0l, *w1h, *w1l, *wch, *wcl;
    int2 *tap0, *tap1, *tapc;
    cudaGetSymbolAddress((void**)&xn,  g_xn);
    cudaGetSymbolAddress((void**)&h0a, g_h0a);
    cudaGetSymbolAddress((void**)&h0b, g_h0b);
    cudaGetSymbolAddress((void**)&h1a, g_h1a);
    cudaGetSymbolAddress((void**)&h1b, g_h1b);
    cudaGetSymbolAddress((void**)&c0,  g_c0);
    cudaGetSymbolAddress((void**)&c1,  g_c1);
    cudaGetSymbolAddress((void**)&y,   g_y);
    cudaGetSymbolAddress((void**)&pool, g_pool);
    cudaGetSymbolAddress((void**)&f1, g_f1);
    cudaGetSymbolAddress((void**)&f2, g_f2);
    cudaGetSymbolAddress((void**)&f3, g_f3);
    cudaGetSymbolAddress((void**)&w0h, g_w0h);
    cudaGetSymbolAddress((void**)&w0l, g_w0l);
    cudaGetSymbolAddress((void**)&w1h, g_w1h);
    cudaGetSymbolAddress((void**)&w1l, g_w1l);
    cudaGetSymbolAddress((void**)&wch, g_wch);
    cudaGetSymbolAddress((void**)&wcl, g_wcl);
    cudaGetSymbolAddress((void**)&tap0, g_tap0);
    cudaGetSymbolAddress((void**)&tap1, g_tap1);
    cudaGetSymbolAddress((void**)&tapc, g_tapc);

    // EPI0: BUF = 2*8192 + 2*8192 = 32768; total 2*BUF + taps + staging = 110080
    const int SMEM0 = 2 * 32768 + TAPSZ + 128 * 36 * 4 + 128 * 33 * 4;  // 110080
    // EPI1: BUF = 2*8192 + 2*4096 = 24576
    const int SMEM1 = 2 * 24576 + TAPSZ + 128 * 36 * 4 + 128 * 33 * 4;  // 93696
    cudaFuncSetAttribute(convmma_kernel<4, 0>, cudaFuncAttributeMaxDynamicSharedMemorySize, SMEM0);
    cudaFuncSetAttribute(convmma_kernel<2, 1>, cudaFuncAttributeMaxDynamicSharedMemorySize, SMEM1);

    zero_all_kernel<<<(int)((NXZ + 255) / 256), 256>>>(xn, h0a, h0b, h1a, h1b, c0, c1);

    const int nln = BATCH * TSTEPS * NPIX;
    ln_kernel<<<(nln + 255) / 256, 256>>>(x, lg, lb, xn);

    const int nprep = GATES * K0PAD + GATES * K1PAD + HID * KCPAD + K0PAD + K1PAD + KCPAD;
    prep_kernel<<<(nprep + 255) / 256, 256>>>(w0, w1, wc);

    uint32_t* h0buf[2] = {h0a, h0b};
    uint32_t* h1buf[2] = {h1a, h1b};
    dim3 grid0(5, BATCH, 2);
    for (int t = 0; t < TSTEPS; t++) {
        int r = t & 1;
        const uint32_t* xt = xn + (long)t * BATCH * (CIN + 1) * PPLANE;
        convmma_kernel<4, 0><<<grid0, 256, SMEM0>>>(
            xt, CIN, h0buf[r], HID, tap0, w0h, w0l, K0PAD, b0, h0buf[1 - r], c0);
        convmma_kernel<4, 0><<<grid0, 256, SMEM0>>>(
            h0buf[1 - r], HID, h1buf[r], HID, tap1, w1h, w1l, K1PAD, b1, h1buf[1 - r], c1);
    }
    const uint32_t* hfin = h1buf[0];   // t=19 (r=1) wrote h1buf[0]

    dim3 grid1(5, BATCH, 1);
    convmma_kernel<2, 1><<<grid1, 128, SMEM1>>>(
        hfin, HID, hfin, HID, tapc, wch, wcl, KCPAD, bc, y, (float*)0);

    const int npool = BATCH * HID * POOLD * POOLD;
    pool_kernel<<<(npool + 255) / 256, 256>>>(y, pool);
    {
        int warps = BATCH * FC1N;
        fc_kernel<<<(warps * 32 + 255) / 256, 256>>>(pool, wf1, bf1, f1, BATCH, FC1N, FEAT, 1);
    }
    {
        int warps = BATCH * FC2N;
        fc_kernel<<<(warps * 32 + 255) / 256, 256>>>(f1, wf2, bf2, f2, BATCH, FC2N, FC1N, 1);
    }
    {
        int warps = BATCH * 2;
        fc_kernel<<<(warps * 32 + 255) / 256, 256>>>(f2, wf3, bf3, f3, BATCH, 2, FC2N, 0);
    }
    lsm_kernel<<<1, BATCH>>>(f3, out);
}